// round 4
// baseline (speedup 1.0000x reference)
#include <cuda_runtime.h>
#include <cstdint>

#define Td 4
#define Bd 32
#define Cd 384
#define HWd 256
#define NTOT 32768          // Td*Bd*HWd
#define HEADS 8
#define CHD 48
#define EPSB 1e-5f
#define NELEM 12582912
#define ROWS3 1152
#define ROWS4 1536
#define INV1 (1.0f / 254.0f)
#define INV2 (1.0f / 64516.0f)

// ---- scratch ----
__device__ int8_t g_sx[(size_t)NTOT * Cd];        // shortcut spikes [j][c]
__device__ float  g_z[(size_t)NTOT * ROWS3];      // qkv pre-acts [j][row]
__device__ int8_t g_sqkv[(size_t)NTOT * ROWS3];   // q|k|v spikes [j][row]
__device__ int8_t g_y[(size_t)NTOT * Cd];         // y = q*kv [j][c]
__device__ float  g_kvpart[128 * 4 * Cd];
__device__ int8_t g_kvs[128 * Cd];                // [tb][c]
__device__ int8_t g_w8[3][ROWS4][Cd];             // quantized weight terms
__device__ float  g_srow[ROWS4];                  // per-row quant scale
__device__ float  g_scale[ROWS4];
__device__ float  g_bias[ROWS4];

// ---- helpers ----
__device__ __forceinline__ uint32_t smem_u32(const void* p) {
    uint32_t a;
    asm("{ .reg .u64 t; cvta.to.shared.u64 t, %1; cvt.u32.u64 %0, t; }" : "=r"(a) : "l"(p));
    return a;
}
__device__ __forceinline__ void cp16(uint32_t d, const void* s) {
    asm volatile("cp.async.cg.shared.global [%0], [%1], 16;" :: "r"(d), "l"(s));
}
__device__ __forceinline__ void cp_commit() {
    asm volatile("cp.async.commit_group;" ::: "memory");
}
template <int N>
__device__ __forceinline__ void cp_wait() {
    asm volatile("cp.async.wait_group %0;" :: "n"(N) : "memory");
}
__device__ __forceinline__ void ldsm_x4(uint32_t& r0, uint32_t& r1, uint32_t& r2, uint32_t& r3,
                                        uint32_t a) {
    asm volatile("ldmatrix.sync.aligned.m8n8.x4.shared.b16 {%0,%1,%2,%3},[%4];"
                 : "=r"(r0), "=r"(r1), "=r"(r2), "=r"(r3) : "r"(a));
}
__device__ __forceinline__ void mma_s8(int* d, const uint32_t* a, uint32_t b0, uint32_t b1) {
    asm volatile("mma.sync.aligned.m16n8k32.row.col.s32.s8.s8.s32 "
                 "{%0,%1,%2,%3},{%4,%5,%6,%7},{%8,%9},{%0,%1,%2,%3};"
                 : "+r"(d[0]), "+r"(d[1]), "+r"(d[2]), "+r"(d[3])
                 : "r"(a[0]), "r"(a[1]), "r"(a[2]), "r"(a[3]), "r"(b0), "r"(b1));
}
// swizzled offset: 32B logical rows packed 4-per-128B physical row, 3-bit xor
__device__ __forceinline__ int aoff(int r, int kc) {
    int p = (((r & 3) << 1) | kc) ^ ((r >> 2) & 7);
    return ((r >> 2) << 7) | (p << 4);
}

// ---------------------------------------------------------------------------
// int8 tensor-core GEMM: D[j, col] = sum_c A[j,c] * W[col,c] (3 quant terms)
// A: spikes [j][384] s8.  B: g_w8 terms [row_off+col][384] s8.
// MODE 0: z[j][1152] = D*scale+bias.  MODE 1: scatter (t,b,c,n) + identity.
// Block 128(j) x 64(col); warps 2x4; warp 64x16; 4-stage cp.async, k-chunk 32.
// ---------------------------------------------------------------------------
template <int MODE>
__global__ void __launch_bounds__(256) imma_gemm(
    const int8_t* __restrict__ Amat, float* __restrict__ out,
    int row_off, const float* __restrict__ identity)
{
    __shared__ __align__(16) char smem[40960];     // 4*4096 (A) + 4*6144 (B)
    const int tid = threadIdx.x, lane = tid & 31, warp = tid >> 5;
    const int wmj = warp >> 2, wn = warp & 3;
    const int j0 = blockIdx.x * 128;
    const int nb0 = blockIdx.y * 64;
    const int wrow0 = row_off + nb0;

    const uint32_t sAu = smem_u32(smem);
    const uint32_t sBu = sAu + 16384;
    const int8_t* w8 = &g_w8[0][0][0];

    int iacc[3][4][2][4];
#pragma unroll
    for (int t = 0; t < 3; t++)
#pragma unroll
        for (int mt = 0; mt < 4; mt++)
#pragma unroll
            for (int nt = 0; nt < 2; nt++)
#pragma unroll
                for (int i = 0; i < 4; i++) iacc[t][mt][nt][i] = 0;

    const int la_r = tid >> 1, la_h = tid & 1;

    auto issue = [&](int ch) {
        int s = ch & 3, k0 = ch << 5;
        cp16(sAu + s * 4096 + aoff(la_r, la_h),
             Amat + (size_t)(j0 + la_r) * Cd + k0 + la_h * 16);
        {
            int t = tid >> 7, rr = (tid & 127) >> 1, h = tid & 1;
            cp16(sBu + s * 6144 + t * 2048 + aoff(rr, h),
                 w8 + ((size_t)t * ROWS4 + wrow0 + rr) * Cd + k0 + h * 16);
        }
        if (tid < 128) {
            int rr = tid >> 1, h = tid & 1;
            cp16(sBu + s * 6144 + 2 * 2048 + aoff(rr, h),
                 w8 + ((size_t)2 * ROWS4 + wrow0 + rr) * Cd + k0 + h * 16);
        }
        cp_commit();
    };

    const int g = lane >> 3, lr = lane & 7;
    const int arow_b = wmj * 64 + ((g & 1) << 3) + lr;
    const int brow = wn * 16 + ((g & 1) << 3) + lr;
    const int kc = g >> 1;

    auto compute = [&](int s) {
        uint32_t ab = sAu + s * 4096, bb = sBu + s * 6144;
        uint32_t af[4][4];
#pragma unroll
        for (int mt = 0; mt < 4; mt++)
            ldsm_x4(af[mt][0], af[mt][1], af[mt][2], af[mt][3],
                    ab + aoff(arow_b + mt * 16, kc));
#pragma unroll
        for (int t = 0; t < 3; t++) {
            uint32_t b0, b1, b2, b3;
            ldsm_x4(b0, b1, b2, b3, bb + t * 2048 + aoff(brow, kc));
#pragma unroll
            for (int mt = 0; mt < 4; mt++) {
                mma_s8(iacc[t][mt][0], af[mt], b0, b2);
                mma_s8(iacc[t][mt][1], af[mt], b1, b3);
            }
        }
    };

    issue(0); issue(1); issue(2);
#pragma unroll
    for (int ch = 0; ch < 12; ch++) {
        int rem = 11 - ch;
        if (rem >= 2) cp_wait<2>(); else if (rem == 1) cp_wait<1>(); else cp_wait<0>();
        __syncthreads();
        compute(ch & 3);
        __syncthreads();
        if (ch + 3 < 12) issue(ch + 3);
    }

    // ---- epilogue ----
    float* sE = reinterpret_cast<float*>(smem);    // MODE1 staging [128][65]
    const int rbase = j0 + wmj * 64 + (lane >> 2);
#pragma unroll
    for (int mt = 0; mt < 4; mt++) {
#pragma unroll
        for (int nt = 0; nt < 2; nt++) {
            int col0 = nb0 + wn * 16 + nt * 8 + ((lane & 3) << 1);
            float sc0 = g_srow[row_off + col0] * g_scale[row_off + col0];
            float sc1 = g_srow[row_off + col0 + 1] * g_scale[row_off + col0 + 1];
            float bi0 = g_bias[row_off + col0], bi1 = g_bias[row_off + col0 + 1];
            const int* A1 = iacc[0][mt][nt];
            const int* A2 = iacc[1][mt][nt];
            const int* A3 = iacc[2][mt][nt];
            float v[4];
#pragma unroll
            for (int i = 0; i < 4; i++) {
                float sc = (i & 1) ? sc1 : sc0, bi = (i & 1) ? bi1 : bi0;
                v[i] = fmaf(sc, (float)A1[i],
                       fmaf(sc * INV1, (float)A2[i],
                       fmaf(sc * INV2, (float)A3[i], bi)));
            }
            int r0 = rbase + mt * 16, r1 = r0 + 8;
            if (MODE == 0) {
                *reinterpret_cast<float2*>(&out[(size_t)r0 * ROWS3 + col0]) =
                    make_float2(v[0], v[1]);
                *reinterpret_cast<float2*>(&out[(size_t)r1 * ROWS3 + col0]) =
                    make_float2(v[2], v[3]);
            } else {
                int cl = col0 - nb0;
                sE[(r0 - j0) * 65 + cl] = v[0];
                sE[(r0 - j0) * 65 + cl + 1] = v[1];
                sE[(r1 - j0) * 65 + cl] = v[2];
                sE[(r1 - j0) * 65 + cl + 1] = v[3];
            }
        }
    }
    if (MODE == 1) {
        __syncthreads();
#pragma unroll
        for (int it = 0; it < 32; it++) {
            int idx = tid + it * 256;
            int jl = idx & 127, cl = idx >> 7;
            int j = j0 + jl;
            int tb = j >> 8, n = j & 255;
            int c = nb0 + cl;
            size_t oi = ((size_t)tb * Cd + c) * HWd + n;
            out[oi] = sE[jl * 65 + cl] + identity[oi];
        }
    }
}

// ---------------------------------------------------------------------------
__global__ void prep_kernel(
    const float* qg, const float* qb, const float* qm, const float* qv,
    const float* kg, const float* kb, const float* km, const float* kvv,
    const float* vg, const float* vb, const float* vm, const float* vvv,
    const float* pb, const float* pg, const float* pbe, const float* pm, const float* pv)
{
    int d = threadIdx.x;
    if (d >= Cd) return;
    float s;
    s = qg[d] * rsqrtf(qv[d] + EPSB);  g_scale[d]        = s; g_bias[d]        = qb[d] - qm[d] * s;
    s = kg[d] * rsqrtf(kvv[d] + EPSB); g_scale[Cd + d]   = s; g_bias[Cd + d]   = kb[d] - km[d] * s;
    s = vg[d] * rsqrtf(vvv[d] + EPSB); g_scale[2*Cd + d] = s; g_bias[2*Cd + d] = vb[d] - vm[d] * s;
    s = pg[d] * rsqrtf(pv[d] + EPSB);  g_scale[3*Cd + d] = s; g_bias[3*Cd + d] = (pb[d] - pm[d]) * s + pbe[d];
}

// per-row 3-term int8 quantization, block per row (128 threads)
__global__ void wsplit_kernel(const float* __restrict__ qw, const float* __restrict__ kw,
                              const float* __restrict__ vw, const float* __restrict__ pw)
{
    __shared__ float red[4];
    __shared__ float ssh;
    int row = blockIdx.x;
    int tid = threadIdx.x;
    const float* src = (row < Cd) ? qw : (row < 2*Cd) ? kw : (row < 3*Cd) ? vw : pw;
    const float* wr = src + (size_t)(row % Cd) * Cd;

    float m = 0.f;
    for (int c = tid; c < Cd; c += 128) m = fmaxf(m, fabsf(wr[c]));
#pragma unroll
    for (int o = 16; o > 0; o >>= 1) m = fmaxf(m, __shfl_xor_sync(0xffffffffu, m, o));
    if ((tid & 31) == 0) red[tid >> 5] = m;
    __syncthreads();
    if (tid == 0) {
        float mm = fmaxf(fmaxf(red[0], red[1]), fmaxf(red[2], red[3]));
        ssh = fmaxf(mm, 1e-20f) / 127.f;
        g_srow[row] = ssh;
    }
    __syncthreads();
    float s = ssh, inv_s = 1.f / s;
    for (int c = tid; c < Cd; c += 128) {
        float a = wr[c] * inv_s;
        float q1 = fminf(fmaxf(rintf(a), -127.f), 127.f);
        float r1 = a - q1;
        float q2 = fminf(fmaxf(rintf(r1 * 254.f), -127.f), 127.f);
        float r2 = r1 - q2 * INV1;
        float q3 = fminf(fmaxf(rintf(r2 * 64516.f), -127.f), 127.f);
        g_w8[0][row][c] = (int8_t)q1;
        g_w8[1][row][c] = (int8_t)q2;
        g_w8[2][row][c] = (int8_t)q3;
    }
}

// ---------------------------------------------------------------------------
// xs = lif(x) -> g_sx[j][c] s8, smem transpose
// ---------------------------------------------------------------------------
__global__ void lif_x_kernel(const float* __restrict__ x)
{
    __shared__ float sx[Td][64][32];
    __shared__ int8_t ss[Td][64][32];
    int tid = threadIdx.x;
    int n0 = blockIdx.x * 32, c0 = blockIdx.y * 64, b = blockIdx.z;
#pragma unroll
    for (int t = 0; t < Td; t++)
#pragma unroll
        for (int p = 0; p < 8; p++) {
            int c_l = p * 8 + (tid >> 5), n_l = tid & 31;
            sx[t][c_l][n_l] = x[(((size_t)t * Bd + b) * Cd + c0 + c_l) * HWd + n0 + n_l];
        }
    __syncthreads();
#pragma unroll
    for (int s = 0; s < 8; s++) {
        int pt = tid + s * 256;
        int c_l = pt >> 5, n_l = pt & 31;
        float v = 0.f;
#pragma unroll
        for (int t = 0; t < Td; t++) {
            v = 0.5f * (v + sx[t][c_l][n_l]);
            float sp = (v >= 1.0f) ? 1.f : 0.f;
            v *= (1.f - sp);
            ss[t][c_l][n_l] = (int8_t)sp;
        }
    }
    __syncthreads();
#pragma unroll
    for (int t = 0; t < Td; t++)
#pragma unroll
        for (int s = 0; s < 8; s++) {
            int idx = tid + s * 256;
            int c_l = idx & 63, n_l = idx >> 6;
            g_sx[((size_t)(t * Bd + b) * HWd + n0 + n_l) * Cd + c0 + c_l] = ss[t][c_l][n_l];
        }
}

// ---------------------------------------------------------------------------
__global__ void lif_t_kernel()
{
    int gid = blockIdx.x * 256 + threadIdx.x;      // 8192*1152 exact
    int bn = gid / ROWS3, row = gid - bn * ROWS3;
    float v = 0.f;
#pragma unroll
    for (int t = 0; t < Td; t++) {
        size_t j = (size_t)t * 8192 + bn;
        float xv = g_z[j * ROWS3 + row];
        v = 0.5f * (v + xv);
        float s = (v >= 1.0f) ? 1.f : 0.f;
        v *= (1.f - s);
        g_sqkv[j * ROWS3 + row] = (int8_t)s;
    }
}

__global__ void kvpart_kernel()
{
    int tb = blockIdx.x, nq = blockIdx.y;
    int c = threadIdx.x;                           // 384 threads
    int acc = 0;
    for (int n = nq * 64; n < nq * 64 + 64; n++) {
        size_t base = ((size_t)tb * HWd + n) * ROWS3;
        acc += (int)(g_sqkv[base + Cd + c] & g_sqkv[base + 2 * Cd + c]);
    }
    g_kvpart[(tb * 4 + nq) * Cd + c] = (float)acc;
}

__global__ void kvlif_kernel()
{
    int gid = blockIdx.x * 256 + threadIdx.x;
    if (gid >= Bd * Cd) return;
    int b = gid / Cd, c = gid - b * Cd;
    float v = 0.f;
#pragma unroll
    for (int t = 0; t < Td; t++) {
        int tb = t * Bd + b;
        float kvp = 0.f;
#pragma unroll
        for (int nq = 0; nq < 4; nq++) kvp += g_kvpart[(tb * 4 + nq) * Cd + c];
        v = 0.5f * (v + kvp);
        float s = (v >= 0.5f) ? 1.f : 0.f;
        v *= (1.f - s);
        g_kvs[tb * Cd + c] = (int8_t)s;
    }
}

__global__ void y_kernel()
{
    int tid = blockIdx.x * 256 + threadIdx.x;      // NTOT*Cd exact
    int j = tid / Cd, c = tid - j * Cd;
    g_y[tid] = g_sqkv[(size_t)j * ROWS3 + c] & g_kvs[(j >> 8) * Cd + c];
}

__global__ void vout_kernel(float* __restrict__ out2)
{
    int tid = blockIdx.x * 256 + threadIdx.x;      // NELEM exact
    int ch = tid % CHD;
    int rest = tid / CHD;
    int n = rest % HWd;  rest /= HWd;
    int head = rest % HEADS;
    int tb = rest / HEADS;
    int c = head * CHD + ch;
    out2[tid] = (float)g_sqkv[((size_t)tb * HWd + n) * ROWS3 + 2 * Cd + c];
}

// ---------------------------------------------------------------------------
extern "C" void kernel_launch(void* const* d_in, const int* in_sizes, int n_in,
                              void* d_out, int out_size)
{
    const float* x   = (const float*)d_in[0];
    const float* qw  = (const float*)d_in[1];
    const float* qg  = (const float*)d_in[2];
    const float* qb  = (const float*)d_in[3];
    const float* qm  = (const float*)d_in[4];
    const float* qv  = (const float*)d_in[5];
    const float* kw  = (const float*)d_in[6];
    const float* kg  = (const float*)d_in[7];
    const float* kb  = (const float*)d_in[8];
    const float* km  = (const float*)d_in[9];
    const float* kv  = (const float*)d_in[10];
    const float* vw  = (const float*)d_in[11];
    const float* vg  = (const float*)d_in[12];
    const float* vb  = (const float*)d_in[13];
    const float* vm  = (const float*)d_in[14];
    const float* vv  = (const float*)d_in[15];
    const float* pw  = (const float*)d_in[16];
    const float* pb  = (const float*)d_in[17];
    const float* pg  = (const float*)d_in[18];
    const float* pbe = (const float*)d_in[19];
    const float* pm  = (const float*)d_in[20];
    const float* pv  = (const float*)d_in[21];

    int8_t *p_sx, *p_sy;
    float *p_z;
    cudaGetSymbolAddress((void**)&p_sx, g_sx);
    cudaGetSymbolAddress((void**)&p_sy, g_y);
    cudaGetSymbolAddress((void**)&p_z, g_z);

    float* out = (float*)d_out;

    prep_kernel<<<1, 384>>>(qg, qb, qm, qv, kg, kb, km, kv, vg, vb, vm, vv,
                            pb, pg, pbe, pm, pv);
    wsplit_kernel<<<ROWS4, 128>>>(qw, kw, vw, pw);
    lif_x_kernel<<<dim3(HWd / 32, Cd / 64, Bd), 256>>>(x);

    imma_gemm<0><<<dim3(NTOT / 128, ROWS3 / 64), 256>>>(p_sx, p_z, 0, nullptr);
    lif_t_kernel<<<8192 * ROWS3 / 256, 256>>>();

    kvpart_kernel<<<dim3(128, 4), Cd>>>();
    kvlif_kernel<<<48, 256>>>();
    y_kernel<<<(size_t)NTOT * Cd / 256, 256>>>();

    imma_gemm<1><<<dim3(NTOT / 128, Cd / 64), 256>>>(p_sy, out, ROWS3, x);

    if (out_size >= 2 * NELEM)
        vout_kernel<<<NELEM / 256, 256>>>(out + NELEM);
}

// round 5
// speedup vs baseline: 3.3055x; 3.3055x over previous
#include <cuda_runtime.h>
#include <cuda_fp16.h>
#include <cstdint>

#define Td 4
#define Bd 32
#define Cd 384
#define HWd 256
#define NTOT 32768          // Td*Bd*HWd
#define TBN 8192            // Bd*HWd
#define HEADS 8
#define CHD 48
#define EPSB 1e-5f
#define NELEM 12582912      // Td*Bd*Cd*HWd
#define WSC 16384.0f
#define WSCI 6.103515625e-05f   // 1/16384

// ---- scratch (device statics = sanctioned no-alloc workaround) ----
__device__ __half g_sx[Cd * NTOT];            // shortcut-LIF spikes [c][(t*B+b)*HW+n]
__device__ float  g_z[3 * Cd * NTOT];         // qkv conv outputs (BN'ed), rows 0..1151
__device__ __half g_sqkv[3 * Cd * NTOT];      // q,k,v spikes (rows 0..1151)
__device__ __half g_y[Cd * NTOT];             // y = q * kv (binary)
__device__ __half g_kvs[Td * Bd * Cd];        // talking-heads spikes
__device__ __half g_w[2][4 * Cd][Cd];         // 2-term fp16 split weights (x16384)
__device__ float  g_scale[4 * Cd];
__device__ float  g_bias[4 * Cd];

// ---------------------------------------------------------------------------
// PTX helpers
// ---------------------------------------------------------------------------
__device__ __forceinline__ uint32_t cvta_smem(const void* p) {
    uint32_t a;
    asm("{ .reg .u64 t; cvta.to.shared.u64 t, %1; cvt.u32.u64 %0, t; }" : "=r"(a) : "l"(p));
    return a;
}
__device__ __forceinline__ void ldsm_x4(uint32_t& r0, uint32_t& r1, uint32_t& r2, uint32_t& r3, uint32_t a) {
    asm volatile("ldmatrix.sync.aligned.m8n8.x4.shared.b16 {%0,%1,%2,%3},[%4];"
                 : "=r"(r0), "=r"(r1), "=r"(r2), "=r"(r3) : "r"(a));
}
__device__ __forceinline__ void ldsm_x4t(uint32_t& r0, uint32_t& r1, uint32_t& r2, uint32_t& r3, uint32_t a) {
    asm volatile("ldmatrix.sync.aligned.m8n8.x4.trans.shared.b16 {%0,%1,%2,%3},[%4];"
                 : "=r"(r0), "=r"(r1), "=r"(r2), "=r"(r3) : "r"(a));
}
__device__ __forceinline__ void mma_f16(float* d, const uint32_t* a, const uint32_t* b) {
    asm volatile("mma.sync.aligned.m16n8k16.row.col.f32.f16.f16.f32 "
                 "{%0,%1,%2,%3},{%4,%5,%6,%7},{%8,%9},{%0,%1,%2,%3};"
                 : "+f"(d[0]), "+f"(d[1]), "+f"(d[2]), "+f"(d[3])
                 : "r"(a[0]), "r"(a[1]), "r"(a[2]), "r"(a[3]), "r"(b[0]), "r"(b[1]));
}

// ---------------------------------------------------------------------------
// BN fold
// ---------------------------------------------------------------------------
__global__ void prep_kernel(
    const float* qg, const float* qb, const float* qm, const float* qv,
    const float* kg, const float* kb, const float* km, const float* kvv,
    const float* vg, const float* vb, const float* vm, const float* vvv,
    const float* pb, const float* pg, const float* pbe, const float* pm, const float* pv)
{
    int d = threadIdx.x;
    if (d >= Cd) return;
    float s;
    s = qg[d] * rsqrtf(qv[d] + EPSB);  g_scale[d]          = s; g_bias[d]          = qb[d] - qm[d] * s;
    s = kg[d] * rsqrtf(kvv[d] + EPSB); g_scale[Cd + d]     = s; g_bias[Cd + d]     = kb[d] - km[d] * s;
    s = vg[d] * rsqrtf(vvv[d] + EPSB); g_scale[2*Cd + d]   = s; g_bias[2*Cd + d]   = vb[d] - vm[d] * s;
    s = pg[d] * rsqrtf(pv[d] + EPSB);  g_scale[3*Cd + d]   = s; g_bias[3*Cd + d]   = (pb[d] - pm[d]) * s + pbe[d];
}

// 2-term fp16 split of the four weight matrices, pre-scaled by 2^14
__global__ void wsplit_kernel(const float* __restrict__ qw, const float* __restrict__ kw,
                              const float* __restrict__ vw, const float* __restrict__ pw)
{
    int tid = blockIdx.x * 256 + threadIdx.x;      // 1536*384 exact
    int row = tid / Cd, cin = tid - row * Cd;
    const float* src = (row < Cd) ? qw : (row < 2*Cd) ? kw : (row < 3*Cd) ? vw : pw;
    float a = src[(row % Cd) * Cd + cin] * WSC;
    __half h1 = __float2half_rn(a);
    float r1 = a - __half2float(h1);
    g_w[0][row][cin] = h1;
    g_w[1][row][cin] = __float2half_rn(r1);
}

// ---------------------------------------------------------------------------
// xs = lif(x), write fp16 spikes in [c][(t*B+b)*HW+n]
// ---------------------------------------------------------------------------
__global__ void lif_x_kernel(const float* __restrict__ x)
{
    int tid = blockIdx.x * 256 + threadIdx.x;      // Bd*Cd*HWd exact
    int n = tid % HWd;
    int c = (tid / HWd) % Cd;
    int b = tid / (HWd * Cd);
    float v = 0.f;
#pragma unroll
    for (int t = 0; t < Td; t++) {
        float xv = x[(size_t)((t * Bd + b) * Cd + c) * HWd + n];
        v = 0.5f * (v + xv);
        float s = (v >= 1.0f) ? 1.f : 0.f;
        v *= (1.f - s);
        g_sx[(size_t)c * NTOT + (size_t)(t * Bd + b) * HWd + n] = __float2half(s);
    }
}

// ---------------------------------------------------------------------------
// Tensor-core GEMM: out[row, j] = sum_c (h1+h2)[row,c] * B[c, j] * 2^-14
// Block tile 128x128xBK32, warps 2(M)x4(N), warp tile 64x32, 2 weight terms.
// MODE 0: out fp32 [row][NTOT] = acc*scale+bias
// MODE 1: scatter to (t,b,c,n), add identity (proj + residual)
// ---------------------------------------------------------------------------
template <int MODE>
__global__ void __launch_bounds__(256, 2) mma_gemm(
    const __half* __restrict__ Bmat, float* __restrict__ out,
    int row_off, const float* __restrict__ identity)
{
    __shared__ alignas(16) __half As[2][128][40];   // +8 pad
    __shared__ alignas(16) __half Bs[32][136];      // +8 pad

    const int tid = threadIdx.x;
    const int warp = tid >> 5, lane = tid & 31;
    const int wm0 = (warp >> 2) * 64, wn0 = (warp & 3) * 32;
    const int m_blk = blockIdx.y * 128;
    const int n_blk = blockIdx.x * 128;

    float acc[4][4][4];
#pragma unroll
    for (int i = 0; i < 4; i++)
#pragma unroll
        for (int j = 0; j < 4; j++)
#pragma unroll
            for (int r = 0; r < 4; r++) acc[i][j][r] = 0.f;

    for (int k0 = 0; k0 < Cd; k0 += 32) {
#pragma unroll
        for (int term = 0; term < 2; term++) {
#pragma unroll
            for (int it = 0; it < 2; it++) {
                int idx = (tid + it * 256) * 8;          // elem in 128x32
                int r = idx >> 5, c = idx & 31;
                float4 v4 = *(const float4*)&g_w[term][row_off + m_blk + r][k0 + c];
                *(float4*)&As[term][r][c] = v4;
            }
        }
#pragma unroll
        for (int it = 0; it < 2; it++) {
            int idx = (tid + it * 256) * 8;              // elem in 32x128
            int r = idx >> 7, c = idx & 127;
            float4 v4 = *(const float4*)&Bmat[(size_t)(k0 + r) * NTOT + n_blk + c];
            *(float4*)&Bs[r][c] = v4;
        }
        __syncthreads();

#pragma unroll
        for (int ks = 0; ks < 2; ks++) {
            const int kk = ks * 16;
            uint32_t bfrag[4][2];
#pragma unroll
            for (int h = 0; h < 2; h++) {
                uint32_t r0, r1, r2, r3;
                uint32_t a = cvta_smem(&Bs[kk + (lane & 15)][wn0 + h * 16 + (lane >> 4) * 8]);
                ldsm_x4t(r0, r1, r2, r3, a);
                bfrag[h * 2][0] = r0;     bfrag[h * 2][1] = r1;
                bfrag[h * 2 + 1][0] = r2; bfrag[h * 2 + 1][1] = r3;
            }
#pragma unroll
            for (int term = 0; term < 2; term++) {
#pragma unroll
                for (int mt = 0; mt < 4; mt++) {
                    uint32_t afrag[4];
                    uint32_t a = cvta_smem(&As[term][wm0 + mt * 16 + (lane & 15)][kk + (lane >> 4) * 8]);
                    ldsm_x4(afrag[0], afrag[1], afrag[2], afrag[3], a);
#pragma unroll
                    for (int nt = 0; nt < 4; nt++)
                        mma_f16(acc[mt][nt], afrag, bfrag[nt]);
                }
            }
        }
        __syncthreads();
    }

    const int g = lane >> 2, tig = lane & 3;
#pragma unroll
    for (int mt = 0; mt < 4; mt++) {
#pragma unroll
        for (int i = 0; i < 2; i++) {
            int row = m_blk + wm0 + mt * 16 + g + i * 8;
            float sc = g_scale[row_off + row] * WSCI;
            float bi = g_bias[row_off + row];
#pragma unroll
            for (int nt = 0; nt < 4; nt++) {
#pragma unroll
                for (int j = 0; j < 2; j++) {
                    int col = n_blk + wn0 + nt * 8 + tig * 2 + j;
                    float val = acc[mt][nt][i * 2 + j] * sc + bi;
                    if (MODE == 0) {
                        out[(size_t)row * NTOT + col] = val;
                    } else {
                        int tb = col >> 8, n = col & 255;
                        size_t oi = ((size_t)tb * Cd + row) * HWd + n;
                        out[oi] = val + identity[oi];
                    }
                }
            }
        }
    }
}

// ---------------------------------------------------------------------------
// Temporal LIF over g_z rows 0..1151 -> fp16 spikes g_sqkv
// ---------------------------------------------------------------------------
__global__ void lif_t_kernel()
{
    int tid = blockIdx.x * 256 + threadIdx.x;    // 1152*TBN exact
    int row = tid / TBN, bn = tid - row * TBN;
    size_t base = (size_t)row * NTOT + bn;
    float v = 0.f;
#pragma unroll
    for (int t = 0; t < Td; t++) {
        float xv = g_z[base + (size_t)t * TBN];
        v = 0.5f * (v + xv);
        float s = (v >= 1.0f) ? 1.f : 0.f;
        v *= (1.f - s);
        g_sqkv[base + (size_t)t * TBN] = __float2half(s);
    }
}

// ---------------------------------------------------------------------------
// kv = lif( sum_n k*v , v_th=0.5 ): block per (b,c)
// ---------------------------------------------------------------------------
__global__ void kv_kernel()
{
    int bc = blockIdx.x;
    int c = bc % Cd, b = bc / Cd;
    int n = threadIdx.x;
    float p[Td];
#pragma unroll
    for (int t = 0; t < Td; t++) {
        size_t o = (size_t)(t * Bd + b) * HWd + n;
        float kk = __half2float(g_sqkv[(size_t)(Cd + c) * NTOT + o]);
        float vv = __half2float(g_sqkv[(size_t)(2 * Cd + c) * NTOT + o]);
        p[t] = kk * vv;
    }
#pragma unroll
    for (int t = 0; t < Td; t++)
        for (int o = 16; o > 0; o >>= 1) p[t] += __shfl_down_sync(0xffffffffu, p[t], o);
    __shared__ float wsum[Td][8];
    int lane = n & 31, wid = n >> 5;
    if (lane == 0)
#pragma unroll
        for (int t = 0; t < Td; t++) wsum[t][wid] = p[t];
    __syncthreads();
    if (n == 0) {
        float v = 0.f;
#pragma unroll
        for (int t = 0; t < Td; t++) {
            float kvp = 0.f;
#pragma unroll
            for (int w = 0; w < 8; w++) kvp += wsum[t][w];
            v = 0.5f * (v + kvp);
            float s = (v >= 0.5f) ? 1.f : 0.f;
            v *= (1.f - s);
            g_kvs[(size_t)(t * Bd + b) * Cd + c] = __float2half(s);
        }
    }
}

// ---------------------------------------------------------------------------
// y = q * kv (binary product, exact in fp16)
// ---------------------------------------------------------------------------
__global__ void y_kernel()
{
    int tid = blockIdx.x * 256 + threadIdx.x;    // Cd*NTOT exact
    int c = tid / NTOT;
    int j = tid - c * NTOT;
    int tb = j >> 8;
    float q = __half2float(g_sqkv[tid]);         // q rows are first
    float kv = __half2float(g_kvs[(size_t)tb * Cd + c]);
    g_y[tid] = __float2half(q * kv);
}

// ---------------------------------------------------------------------------
// Second output: v spikes in (T,B,heads,N,Ch) layout (fp32)
// ---------------------------------------------------------------------------
__global__ void vout_kernel(float* __restrict__ out2)
{
    int tid = blockIdx.x * 256 + threadIdx.x;    // NELEM exact
    int ch = tid % CHD;
    int rest = tid / CHD;
    int n = rest % HWd;
    rest /= HWd;
    int head = rest % HEADS;
    int tb = rest / HEADS;
    int c = head * CHD + ch;
    out2[tid] = __half2float(g_sqkv[(size_t)(2 * Cd + c) * NTOT + (size_t)tb * HWd + n]);
}

// ---------------------------------------------------------------------------
extern "C" void kernel_launch(void* const* d_in, const int* in_sizes, int n_in,
                              void* d_out, int out_size)
{
    const float* x   = (const float*)d_in[0];
    const float* qw  = (const float*)d_in[1];
    const float* qg  = (const float*)d_in[2];
    const float* qb  = (const float*)d_in[3];
    const float* qm  = (const float*)d_in[4];
    const float* qv  = (const float*)d_in[5];
    const float* kw  = (const float*)d_in[6];
    const float* kg  = (const float*)d_in[7];
    const float* kb  = (const float*)d_in[8];
    const float* km  = (const float*)d_in[9];
    const float* kv  = (const float*)d_in[10];
    const float* vw  = (const float*)d_in[11];
    const float* vg  = (const float*)d_in[12];
    const float* vb  = (const float*)d_in[13];
    const float* vm  = (const float*)d_in[14];
    const float* vv  = (const float*)d_in[15];
    const float* pw  = (const float*)d_in[16];
    const float* pb  = (const float*)d_in[17];
    const float* pg  = (const float*)d_in[18];
    const float* pbe = (const float*)d_in[19];
    const float* pm  = (const float*)d_in[20];
    const float* pv  = (const float*)d_in[21];

    __half *p_sx, *p_sy;
    float *p_z;
    cudaGetSymbolAddress((void**)&p_sx, g_sx);
    cudaGetSymbolAddress((void**)&p_sy, g_y);
    cudaGetSymbolAddress((void**)&p_z, g_z);

    float* out = (float*)d_out;

    prep_kernel<<<1, 384>>>(qg, qb, qm, qv, kg, kb, km, kv, vg, vb, vm, vv,
                            pb, pg, pbe, pm, pv);
    wsplit_kernel<<<2304, 256>>>(qw, kw, vw, pw);
    lif_x_kernel<<<12288, 256>>>(x);

    dim3 g1(NTOT / 128, 9);                       // M=1152 stacked q,k,v
    mma_gemm<0><<<g1, 256>>>(p_sx, p_z, 0, nullptr);
    lif_t_kernel<<<36864, 256>>>();

    kv_kernel<<<Bd * Cd, 256>>>();
    y_kernel<<<Cd * NTOT / 256, 256>>>();

    dim3 g2(NTOT / 128, 3);                       // proj: M=384
    mma_gemm<1><<<g2, 256>>>(p_sy, out, 3 * Cd, x);

    if (out_size >= 2 * NELEM)
        vout_kernel<<<NELEM / 256, 256>>>(out + NELEM);
}

// round 6
// speedup vs baseline: 3.3303x; 1.0075x over previous
#include <cuda_runtime.h>
#include <cuda_fp16.h>
#include <cstdint>

#define Td 4
#define Bd 32
#define Cd 384
#define HWd 256
#define NTOT 32768          // Td*Bd*HWd
#define TBN 8192            // Bd*HWd
#define HEADS 8
#define CHD 48
#define EPSB 1e-5f
#define NELEM 12582912      // Td*Bd*Cd*HWd
#define WSC 16384.0f
#define WSCI 6.103515625e-05f   // 1/16384

// ---- scratch ----
__device__ __half g_sx[Cd * NTOT];            // shortcut-LIF spikes [c][(t*B+b)*HW+n]
__device__ float  g_z[3 * Cd * NTOT];         // qkv conv outputs (BN'ed), rows 0..1151
__device__ __half g_sqkv[3 * Cd * NTOT];      // q,k,v spikes (rows 0..1151)
__device__ __half g_kvs[Td * Bd * Cd];        // talking-heads spikes [tb][c]
__device__ __half g_w[2][4 * Cd][Cd];         // 2-term fp16 split weights (x16384)
__device__ float  g_scale[4 * Cd];
__device__ float  g_bias[4 * Cd];

// ---------------------------------------------------------------------------
__device__ __forceinline__ uint32_t cvta_smem(const void* p) {
    uint32_t a;
    asm("{ .reg .u64 t; cvta.to.shared.u64 t, %1; cvt.u32.u64 %0, t; }" : "=r"(a) : "l"(p));
    return a;
}
__device__ __forceinline__ void ldsm_x4(uint32_t& r0, uint32_t& r1, uint32_t& r2, uint32_t& r3, uint32_t a) {
    asm volatile("ldmatrix.sync.aligned.m8n8.x4.shared.b16 {%0,%1,%2,%3},[%4];"
                 : "=r"(r0), "=r"(r1), "=r"(r2), "=r"(r3) : "r"(a));
}
__device__ __forceinline__ void ldsm_x4t(uint32_t& r0, uint32_t& r1, uint32_t& r2, uint32_t& r3, uint32_t a) {
    asm volatile("ldmatrix.sync.aligned.m8n8.x4.trans.shared.b16 {%0,%1,%2,%3},[%4];"
                 : "=r"(r0), "=r"(r1), "=r"(r2), "=r"(r3) : "r"(a));
}
__device__ __forceinline__ void mma_f16(float* d, const uint32_t* a, const uint32_t* b) {
    asm volatile("mma.sync.aligned.m16n8k16.row.col.f32.f16.f16.f32 "
                 "{%0,%1,%2,%3},{%4,%5,%6,%7},{%8,%9},{%0,%1,%2,%3};"
                 : "+f"(d[0]), "+f"(d[1]), "+f"(d[2]), "+f"(d[3])
                 : "r"(a[0]), "r"(a[1]), "r"(a[2]), "r"(a[3]), "r"(b[0]), "r"(b[1]));
}

// ---------------------------------------------------------------------------
__global__ void prep_kernel(
    const float* qg, const float* qb, const float* qm, const float* qv,
    const float* kg, const float* kb, const float* km, const float* kvv,
    const float* vg, const float* vb, const float* vm, const float* vvv,
    const float* pb, const float* pg, const float* pbe, const float* pm, const float* pv)
{
    int d = threadIdx.x;
    if (d >= Cd) return;
    float s;
    s = qg[d] * rsqrtf(qv[d] + EPSB);  g_scale[d]          = s; g_bias[d]          = qb[d] - qm[d] * s;
    s = kg[d] * rsqrtf(kvv[d] + EPSB); g_scale[Cd + d]     = s; g_bias[Cd + d]     = kb[d] - km[d] * s;
    s = vg[d] * rsqrtf(vvv[d] + EPSB); g_scale[2*Cd + d]   = s; g_bias[2*Cd + d]   = vb[d] - vm[d] * s;
    s = pg[d] * rsqrtf(pv[d] + EPSB);  g_scale[3*Cd + d]   = s; g_bias[3*Cd + d]   = (pb[d] - pm[d]) * s + pbe[d];
}

// 2-term fp16 split of the four weight matrices, pre-scaled by 2^14
__global__ void wsplit_kernel(const float* __restrict__ qw, const float* __restrict__ kw,
                              const float* __restrict__ vw, const float* __restrict__ pw)
{
    int tid = blockIdx.x * 256 + threadIdx.x;      // 1536*384 exact
    int row = tid / Cd, cin = tid - row * Cd;
    const float* src = (row < Cd) ? qw : (row < 2*Cd) ? kw : (row < 3*Cd) ? vw : pw;
    float a = src[(row % Cd) * Cd + cin] * WSC;
    __half h1 = __float2half_rn(a);
    float r1 = a - __half2float(h1);
    g_w[0][row][cin] = h1;
    g_w[1][row][cin] = __float2half_rn(r1);
}

// ---------------------------------------------------------------------------
__global__ void lif_x_kernel(const float* __restrict__ x)
{
    int tid = blockIdx.x * 256 + threadIdx.x;      // Bd*Cd*HWd exact
    int n = tid % HWd;
    int c = (tid / HWd) % Cd;
    int b = tid / (HWd * Cd);
    float v = 0.f;
#pragma unroll
    for (int t = 0; t < Td; t++) {
        float xv = x[(size_t)((t * Bd + b) * Cd + c) * HWd + n];
        v = 0.5f * (v + xv);
        float s = (v >= 1.0f) ? 1.f : 0.f;
        v *= (1.f - s);
        g_sx[(size_t)c * NTOT + (size_t)(t * Bd + b) * HWd + n] = __float2half(s);
    }
}

// ---------------------------------------------------------------------------
// Tensor-core GEMM: out[row, j] = sum_c (h1+h2)[row,c] * B[c, j] * 2^-14
// Block tile 128(M) x 256(N) x 32(K); 8 warps as 2(M) x 4(N); warp tile 64x64.
// MODE 0: B = g_sx; out fp32 [row][NTOT] = acc*scale+bias
// MODE 1: B = q-spikes * kv (computed in load); scatter (t,b,c,n) + identity
// ---------------------------------------------------------------------------
template <int MODE>
__global__ void __launch_bounds__(256) mma_gemm(
    const __half* __restrict__ Bmat, float* __restrict__ out,
    int row_off, const float* __restrict__ identity)
{
    __shared__ alignas(16) __half As[2][128][40];    // +8 pad
    __shared__ alignas(16) __half Bs[32][264];       // +8 pad

    const int tid = threadIdx.x;
    const int warp = tid >> 5, lane = tid & 31;
    const int wm0 = (warp >> 2) * 64, wn0 = (warp & 3) * 64;
    const int m_blk = blockIdx.y * 128;
    const int n_blk = blockIdx.x * 256;
    const int tb = n_blk >> 8;                        // constant per CTA

    float acc[4][8][4];
#pragma unroll
    for (int i = 0; i < 4; i++)
#pragma unroll
        for (int j = 0; j < 8; j++)
#pragma unroll
            for (int r = 0; r < 4; r++) acc[i][j][r] = 0.f;

    for (int k0 = 0; k0 < Cd; k0 += 32) {
#pragma unroll
        for (int term = 0; term < 2; term++) {
#pragma unroll
            for (int it = 0; it < 2; it++) {
                int idx = (tid + it * 256) * 8;          // elem in 128x32
                int r = idx >> 5, c = idx & 31;
                float4 v4 = *(const float4*)&g_w[term][row_off + m_blk + r][k0 + c];
                *(float4*)&As[term][r][c] = v4;
            }
        }
#pragma unroll
        for (int it = 0; it < 4; it++) {
            int idx = (tid + it * 256) * 8;              // elem in 32x256
            int r = idx >> 8, c = idx & 255;
            float4 v4 = *(const float4*)&Bmat[(size_t)(k0 + r) * NTOT + n_blk + c];
            if (MODE == 1) {
                __half2 kv2 = __half2half2(g_kvs[(size_t)tb * Cd + k0 + r]);
                __half2* h2 = (__half2*)&v4;
                h2[0] = __hmul2(h2[0], kv2); h2[1] = __hmul2(h2[1], kv2);
                h2[2] = __hmul2(h2[2], kv2); h2[3] = __hmul2(h2[3], kv2);
            }
            *(float4*)&Bs[r][c] = v4;
        }
        __syncthreads();

#pragma unroll
        for (int ks = 0; ks < 2; ks++) {
            const int kk = ks * 16;
            uint32_t bfrag[8][2];
#pragma unroll
            for (int h = 0; h < 4; h++) {
                uint32_t r0, r1, r2, r3;
                uint32_t a = cvta_smem(&Bs[kk + (lane & 15)][wn0 + h * 16 + (lane >> 4) * 8]);
                ldsm_x4t(r0, r1, r2, r3, a);
                bfrag[h * 2][0] = r0;     bfrag[h * 2][1] = r1;
                bfrag[h * 2 + 1][0] = r2; bfrag[h * 2 + 1][1] = r3;
            }
#pragma unroll
            for (int term = 0; term < 2; term++) {
#pragma unroll
                for (int mt = 0; mt < 4; mt++) {
                    uint32_t afrag[4];
                    uint32_t a = cvta_smem(&As[term][wm0 + mt * 16 + (lane & 15)][kk + (lane >> 4) * 8]);
                    ldsm_x4(afrag[0], afrag[1], afrag[2], afrag[3], a);
#pragma unroll
                    for (int nt = 0; nt < 8; nt++)
                        mma_f16(acc[mt][nt], afrag, bfrag[nt]);
                }
            }
        }
        __syncthreads();
    }

    const int g = lane >> 2, tig = lane & 3;
#pragma unroll
    for (int mt = 0; mt < 4; mt++) {
#pragma unroll
        for (int i = 0; i < 2; i++) {
            int row = m_blk + wm0 + mt * 16 + g + i * 8;
            float sc = g_scale[row_off + row] * WSCI;
            float bi = g_bias[row_off + row];
#pragma unroll
            for (int nt = 0; nt < 8; nt++) {
#pragma unroll
                for (int j = 0; j < 2; j++) {
                    int col = n_blk + wn0 + nt * 8 + tig * 2 + j;
                    float val = acc[mt][nt][i * 2 + j] * sc + bi;
                    if (MODE == 0) {
                        out[(size_t)row * NTOT + col] = val;
                    } else {
                        int n = col & 255;
                        size_t oi = ((size_t)tb * Cd + row) * HWd + n;
                        out[oi] = val + identity[oi];
                    }
                }
            }
        }
    }
}

// ---------------------------------------------------------------------------
__global__ void lif_t_kernel()
{
    int tid = blockIdx.x * 256 + threadIdx.x;    // 1152*TBN exact
    int row = tid / TBN, bn = tid - row * TBN;
    size_t base = (size_t)row * NTOT + bn;
    float v = 0.f;
#pragma unroll
    for (int t = 0; t < Td; t++) {
        float xv = g_z[base + (size_t)t * TBN];
        v = 0.5f * (v + xv);
        float s = (v >= 1.0f) ? 1.f : 0.f;
        v *= (1.f - s);
        g_sqkv[base + (size_t)t * TBN] = __float2half(s);
    }
}

// ---------------------------------------------------------------------------
__global__ void kv_kernel()
{
    int bc = blockIdx.x;
    int c = bc % Cd, b = bc / Cd;
    int n = threadIdx.x;
    float p[Td];
#pragma unroll
    for (int t = 0; t < Td; t++) {
        size_t o = (size_t)(t * Bd + b) * HWd + n;
        float kk = __half2float(g_sqkv[(size_t)(Cd + c) * NTOT + o]);
        float vv = __half2float(g_sqkv[(size_t)(2 * Cd + c) * NTOT + o]);
        p[t] = kk * vv;
    }
#pragma unroll
    for (int t = 0; t < Td; t++)
        for (int o = 16; o > 0; o >>= 1) p[t] += __shfl_down_sync(0xffffffffu, p[t], o);
    __shared__ float wsum[Td][8];
    int lane = n & 31, wid = n >> 5;
    if (lane == 0)
#pragma unroll
        for (int t = 0; t < Td; t++) wsum[t][wid] = p[t];
    __syncthreads();
    if (n == 0) {
        float v = 0.f;
#pragma unroll
        for (int t = 0; t < Td; t++) {
            float kvp = 0.f;
#pragma unroll
            for (int w = 0; w < 8; w++) kvp += wsum[t][w];
            v = 0.5f * (v + kvp);
            float s = (v >= 0.5f) ? 1.f : 0.f;
            v *= (1.f - s);
            g_kvs[(size_t)(t * Bd + b) * Cd + c] = __float2half(s);
        }
    }
}

// ---------------------------------------------------------------------------
__global__ void vout_kernel(float* __restrict__ out2)
{
    int tid = blockIdx.x * 256 + threadIdx.x;    // NELEM exact
    int ch = tid % CHD;
    int rest = tid / CHD;
    int n = rest % HWd;
    rest /= HWd;
    int head = rest % HEADS;
    int tb = rest / HEADS;
    int c = head * CHD + ch;
    out2[tid] = __half2float(g_sqkv[(size_t)(2 * Cd + c) * NTOT + (size_t)tb * HWd + n]);
}

// ---------------------------------------------------------------------------
extern "C" void kernel_launch(void* const* d_in, const int* in_sizes, int n_in,
                              void* d_out, int out_size)
{
    const float* x   = (const float*)d_in[0];
    const float* qw  = (const float*)d_in[1];
    const float* qg  = (const float*)d_in[2];
    const float* qb  = (const float*)d_in[3];
    const float* qm  = (const float*)d_in[4];
    const float* qv  = (const float*)d_in[5];
    const float* kw  = (const float*)d_in[6];
    const float* kg  = (const float*)d_in[7];
    const float* kb  = (const float*)d_in[8];
    const float* km  = (const float*)d_in[9];
    const float* kv  = (const float*)d_in[10];
    const float* vw  = (const float*)d_in[11];
    const float* vg  = (const float*)d_in[12];
    const float* vb  = (const float*)d_in[13];
    const float* vm  = (const float*)d_in[14];
    const float* vv  = (const float*)d_in[15];
    const float* pw  = (const float*)d_in[16];
    const float* pb  = (const float*)d_in[17];
    const float* pg  = (const float*)d_in[18];
    const float* pbe = (const float*)d_in[19];
    const float* pm  = (const float*)d_in[20];
    const float* pv  = (const float*)d_in[21];

    __half *p_sx, *p_sq;
    float *p_z;
    cudaGetSymbolAddress((void**)&p_sx, g_sx);
    cudaGetSymbolAddress((void**)&p_sq, g_sqkv);
    cudaGetSymbolAddress((void**)&p_z, g_z);

    float* out = (float*)d_out;

    prep_kernel<<<1, 384>>>(qg, qb, qm, qv, kg, kb, km, kv, vg, vb, vm, vv,
                            pb, pg, pbe, pm, pv);
    wsplit_kernel<<<2304, 256>>>(qw, kw, vw, pw);
    lif_x_kernel<<<12288, 256>>>(x);

    dim3 g1(NTOT / 256, 9);                       // M=1152 stacked q,k,v
    mma_gemm<0><<<g1, 256>>>(p_sx, p_z, 0, nullptr);
    lif_t_kernel<<<36864, 256>>>();

    kv_kernel<<<Bd * Cd, 256>>>();

    dim3 g2(NTOT / 256, 3);                       // proj: M=384, B = q*kv on the fly
    mma_gemm<1><<<g2, 256>>>(p_sq, out, 3 * Cd, x);

    if (out_size >= 2 * NELEM)
        vout_kernel<<<NELEM / 256, 256>>>(out + NELEM);
}

// round 7
// speedup vs baseline: 4.1090x; 1.2338x over previous
#include <cuda_runtime.h>
#include <cuda_fp16.h>
#include <cstdint>

#define Td 4
#define Bd 32
#define Cd 384
#define HWd 256
#define NTOT 32768          // Td*Bd*HWd
#define TBN 8192            // Bd*HWd
#define HEADS 8
#define CHD 48
#define EPSB 1e-5f
#define NELEM 12582912      // Td*Bd*Cd*HWd
#define WSC 16384.0f
#define WSCI 6.103515625e-05f   // 1/16384

#define ASTG 20480          // A stage bytes: 2 terms * 128 rows * 40 halves * 2
#define BSTG 16896          // B stage bytes: 32 rows * 264 halves * 2
#define STG  (ASTG + BSTG)  // 37376
#define NSTAGE 3
#define DSMEM (NSTAGE * STG)

// ---- scratch ----
__device__ __half g_sx[Cd * NTOT];            // shortcut-LIF spikes [c][(t*B+b)*HW+n]
__device__ __half g_sqkv[3 * Cd * NTOT];      // q,k,v spikes (rows 0..1151)
__device__ __half g_kvs[Td * Bd * Cd];        // talking-heads spikes [tb][c]
__device__ __half g_w[2][4 * Cd][Cd];         // 2-term fp16 split weights (x16384)
__device__ float  g_scale[4 * Cd];
__device__ float  g_bias[4 * Cd];

// ---------------------------------------------------------------------------
__device__ __forceinline__ uint32_t cvta_smem(const void* p) {
    uint32_t a;
    asm("{ .reg .u64 t; cvta.to.shared.u64 t, %1; cvt.u32.u64 %0, t; }" : "=r"(a) : "l"(p));
    return a;
}
__device__ __forceinline__ void cp16(uint32_t d, const void* s) {
    asm volatile("cp.async.cg.shared.global [%0], [%1], 16;" :: "r"(d), "l"(s));
}
__device__ __forceinline__ void cp_commit() {
    asm volatile("cp.async.commit_group;" ::: "memory");
}
template <int N>
__device__ __forceinline__ void cp_wait() {
    asm volatile("cp.async.wait_group %0;" :: "n"(N) : "memory");
}
__device__ __forceinline__ void ldsm_x4(uint32_t& r0, uint32_t& r1, uint32_t& r2, uint32_t& r3, uint32_t a) {
    asm volatile("ldmatrix.sync.aligned.m8n8.x4.shared.b16 {%0,%1,%2,%3},[%4];"
                 : "=r"(r0), "=r"(r1), "=r"(r2), "=r"(r3) : "r"(a));
}
__device__ __forceinline__ void ldsm_x4t(uint32_t& r0, uint32_t& r1, uint32_t& r2, uint32_t& r3, uint32_t a) {
    asm volatile("ldmatrix.sync.aligned.m8n8.x4.trans.shared.b16 {%0,%1,%2,%3},[%4];"
                 : "=r"(r0), "=r"(r1), "=r"(r2), "=r"(r3) : "r"(a));
}
__device__ __forceinline__ void mma_f16(float* d, const uint32_t* a, const uint32_t* b) {
    asm volatile("mma.sync.aligned.m16n8k16.row.col.f32.f16.f16.f32 "
                 "{%0,%1,%2,%3},{%4,%5,%6,%7},{%8,%9},{%0,%1,%2,%3};"
                 : "+f"(d[0]), "+f"(d[1]), "+f"(d[2]), "+f"(d[3])
                 : "r"(a[0]), "r"(a[1]), "r"(a[2]), "r"(a[3]), "r"(b[0]), "r"(b[1]));
}

// ---------------------------------------------------------------------------
__global__ void prep_kernel(
    const float* qg, const float* qb, const float* qm, const float* qv,
    const float* kg, const float* kb, const float* km, const float* kvv,
    const float* vg, const float* vb, const float* vm, const float* vvv,
    const float* pb, const float* pg, const float* pbe, const float* pm, const float* pv)
{
    int d = threadIdx.x;
    if (d >= Cd) return;
    float s;
    s = qg[d] * rsqrtf(qv[d] + EPSB);  g_scale[d]          = s; g_bias[d]          = qb[d] - qm[d] * s;
    s = kg[d] * rsqrtf(kvv[d] + EPSB); g_scale[Cd + d]     = s; g_bias[Cd + d]     = kb[d] - km[d] * s;
    s = vg[d] * rsqrtf(vvv[d] + EPSB); g_scale[2*Cd + d]   = s; g_bias[2*Cd + d]   = vb[d] - vm[d] * s;
    s = pg[d] * rsqrtf(pv[d] + EPSB);  g_scale[3*Cd + d]   = s; g_bias[3*Cd + d]   = (pb[d] - pm[d]) * s + pbe[d];
}

__global__ void wsplit_kernel(const float* __restrict__ qw, const float* __restrict__ kw,
                              const float* __restrict__ vw, const float* __restrict__ pw)
{
    int tid = blockIdx.x * 256 + threadIdx.x;      // 1536*384 exact
    int row = tid / Cd, cin = tid - row * Cd;
    const float* src = (row < Cd) ? qw : (row < 2*Cd) ? kw : (row < 3*Cd) ? vw : pw;
    float a = src[(row % Cd) * Cd + cin] * WSC;
    __half h1 = __float2half_rn(a);
    float r1 = a - __half2float(h1);
    g_w[0][row][cin] = h1;
    g_w[1][row][cin] = __float2half_rn(r1);
}

// ---------------------------------------------------------------------------
__global__ void lif_x_kernel(const float* __restrict__ x)
{
    int tid = blockIdx.x * 256 + threadIdx.x;      // Bd*Cd*HWd exact
    int n = tid % HWd;
    int c = (tid / HWd) % Cd;
    int b = tid / (HWd * Cd);
    float v = 0.f;
#pragma unroll
    for (int t = 0; t < Td; t++) {
        float xv = x[(size_t)((t * Bd + b) * Cd + c) * HWd + n];
        v = 0.5f * (v + xv);
        float s = (v >= 1.0f) ? 1.f : 0.f;
        v *= (1.f - s);
        g_sx[(size_t)c * NTOT + (size_t)(t * Bd + b) * HWd + n] = __float2half(s);
    }
}

// ---------------------------------------------------------------------------
// Pipelined tensor-core GEMM, block 128(M) x 256(N) x 32(K), warps 2x4.
// MODE 0 (qkv): B = g_sx; N-tile = one b, 64 n values x 4 timesteps
//   (smem cols interleaved (t,n)); epilogue = temporal LIF -> fp16 spikes.
// MODE 1 (proj): B = q-spikes of one tb (contiguous 256 cols); A fragments
//   multiplied by kv[tb][k] (binary); epilogue = scatter + identity.
// ---------------------------------------------------------------------------
template <int MODE>
__global__ void __launch_bounds__(256) mma_gemm(
    const __half* __restrict__ Bmat, float* __restrict__ out, int row_off)
{
    extern __shared__ char dsm[];
    __shared__ __half skv[Cd];
    const uint32_t sb = cvta_smem(dsm);

    const int tid = threadIdx.x;
    const int warp = tid >> 5, lane = tid & 31;
    const int wm0 = (warp >> 2) * 64, wn0 = (warp & 3) * 64;
    const int m_blk = blockIdx.y * 128;
    // MODE0: blockIdx.x -> (b, n0); MODE1: blockIdx.x = tb
    const int b   = (MODE == 0) ? (blockIdx.x >> 2) : 0;
    const int n0  = (MODE == 0) ? ((blockIdx.x & 3) * 64) : 0;
    const int tb  = (MODE == 1) ? blockIdx.x : 0;
    const int n_blk = (MODE == 1) ? blockIdx.x * 256 : 0;

    if (MODE == 1) {
        for (int i = tid; i < Cd; i += 256) skv[i] = g_kvs[(size_t)tb * Cd + i];
    }

    float acc[4][8][4];
#pragma unroll
    for (int i = 0; i < 4; i++)
#pragma unroll
        for (int j = 0; j < 8; j++)
#pragma unroll
            for (int r = 0; r < 4; r++) acc[i][j][r] = 0.f;

    auto issue = [&](int ch) {
        const uint32_t stg = sb + (ch % NSTAGE) * STG;
        const int k0 = ch * 32;
#pragma unroll
        for (int it = 0; it < 4; it++) {          // A: 1024 cp16
            int o = tid + it * 256;
            int term = o >> 9, rem = o & 511;
            int r = rem >> 2, cq = rem & 3;
            cp16(stg + term * 10240 + r * 80 + cq * 16,
                 &g_w[term][row_off + m_blk + r][k0 + cq * 8]);
        }
#pragma unroll
        for (int it = 0; it < 4; it++) {          // B: 1024 cp16
            int o = tid + it * 256;
            int r = o >> 5, q = o & 31;
            const __half* src;
            if (MODE == 0) {
                int t = (q >> 1) & 3;
                int n = n0 + (q >> 3) * 16 + (q & 1) * 8;
                src = &Bmat[(size_t)(k0 + r) * NTOT + (size_t)(t * Bd + b) * HWd + n];
            } else {
                src = &Bmat[(size_t)(k0 + r) * NTOT + n_blk + q * 8];
            }
            cp16(stg + ASTG + r * 528 + q * 16, src);
        }
        cp_commit();
    };

    auto compute = [&](int ch) {
        const uint32_t stg = sb + (ch % NSTAGE) * STG;
        const int k0 = ch * 32;
#pragma unroll
        for (int ks = 0; ks < 2; ks++) {
            const int kk = ks * 16;
            uint32_t bfrag[8][2];
#pragma unroll
            for (int h = 0; h < 4; h++) {
                uint32_t r0, r1, r2, r3;
                uint32_t a = stg + ASTG + (kk + (lane & 15)) * 528
                           + (wn0 + h * 16 + (lane >> 4) * 8) * 2;
                ldsm_x4t(r0, r1, r2, r3, a);
                bfrag[h * 2][0] = r0;     bfrag[h * 2][1] = r1;
                bfrag[h * 2 + 1][0] = r2; bfrag[h * 2 + 1][1] = r3;
            }
            uint32_t kvlo = 0, kvhi = 0;
            if (MODE == 1) {
                kvlo = *(const uint32_t*)&skv[k0 + kk + (lane & 3) * 2];
                kvhi = *(const uint32_t*)&skv[k0 + kk + 8 + (lane & 3) * 2];
            }
#pragma unroll
            for (int term = 0; term < 2; term++) {
#pragma unroll
                for (int mt = 0; mt < 4; mt++) {
                    uint32_t afrag[4];
                    uint32_t a = stg + term * 10240
                               + (wm0 + mt * 16 + (lane & 15)) * 80
                               + (kk + (lane >> 4) * 8) * 2;
                    ldsm_x4(afrag[0], afrag[1], afrag[2], afrag[3], a);
                    if (MODE == 1) {
                        __half2* af = (__half2*)afrag;
                        __half2 lo = *(__half2*)&kvlo, hi = *(__half2*)&kvhi;
                        af[0] = __hmul2(af[0], lo); af[1] = __hmul2(af[1], lo);
                        af[2] = __hmul2(af[2], hi); af[3] = __hmul2(af[3], hi);
                    }
#pragma unroll
                    for (int nt = 0; nt < 8; nt++)
                        mma_f16(acc[mt][nt], afrag, bfrag[nt]);
                }
            }
        }
    };

    issue(0); issue(1); issue(2);
#pragma unroll
    for (int ch = 0; ch < 12; ch++) {
        int rem = 11 - ch;
        if (rem >= 2) cp_wait<2>(); else if (rem == 1) cp_wait<1>(); else cp_wait<0>();
        __syncthreads();
        compute(ch);
        __syncthreads();
        if (ch + 3 < 12) issue(ch + 3);
    }

    const int g = lane >> 2, tig = lane & 3;
    if (MODE == 0) {
        // temporal LIF across nt pairs: t = nt>>1, local n bit = nt&1
#pragma unroll
        for (int mt = 0; mt < 4; mt++) {
#pragma unroll
            for (int i = 0; i < 2; i++) {
                int row = m_blk + wm0 + mt * 16 + g + i * 8;
                float sc = g_scale[row] * WSCI;
                float bi = g_bias[row];
#pragma unroll
                for (int r = 0; r < 2; r++) {
#pragma unroll
                    for (int j = 0; j < 2; j++) {
                        int n = n0 + (warp & 3) * 16 + r * 8 + tig * 2 + j;
                        float v = 0.f;
#pragma unroll
                        for (int t = 0; t < Td; t++) {
                            float z = acc[mt][2 * t + r][i * 2 + j] * sc + bi;
                            v = 0.5f * (v + z);
                            float s = (v >= 1.0f) ? 1.f : 0.f;
                            v *= (1.f - s);
                            g_sqkv[(size_t)row * NTOT + (size_t)(t * Bd + b) * HWd + n] =
                                __float2half(s);
                        }
                    }
                }
            }
        }
    } else {
        const float* identity = out + NELEM;      // set by caller: identity stored after? no
    }
    if (MODE == 1) {
        // scatter + identity (x) — identity passed via global pointer below
    }
}

// MODE1 epilogue needs identity; specialize with explicit arg instead:
__global__ void __launch_bounds__(256) mma_gemm_proj(
    const __half* __restrict__ Bmat, float* __restrict__ out,
    const float* __restrict__ identity)
{
    extern __shared__ char dsm[];
    __shared__ __half skv[Cd];
    const uint32_t sb = cvta_smem(dsm);
    const int row_off = 3 * Cd;

    const int tid = threadIdx.x;
    const int warp = tid >> 5, lane = tid & 31;
    const int wm0 = (warp >> 2) * 64, wn0 = (warp & 3) * 64;
    const int m_blk = blockIdx.y * 128;
    const int tb = blockIdx.x;
    const int n_blk = tb * 256;

    for (int i = tid; i < Cd; i += 256) skv[i] = g_kvs[(size_t)tb * Cd + i];

    float acc[4][8][4];
#pragma unroll
    for (int i = 0; i < 4; i++)
#pragma unroll
        for (int j = 0; j < 8; j++)
#pragma unroll
            for (int r = 0; r < 4; r++) acc[i][j][r] = 0.f;

    auto issue = [&](int ch) {
        const uint32_t stg = sb + (ch % NSTAGE) * STG;
        const int k0 = ch * 32;
#pragma unroll
        for (int it = 0; it < 4; it++) {
            int o = tid + it * 256;
            int term = o >> 9, rem = o & 511;
            int r = rem >> 2, cq = rem & 3;
            cp16(stg + term * 10240 + r * 80 + cq * 16,
                 &g_w[term][row_off + m_blk + r][k0 + cq * 8]);
        }
#pragma unroll
        for (int it = 0; it < 4; it++) {
            int o = tid + it * 256;
            int r = o >> 5, q = o & 31;
            cp16(stg + ASTG + r * 528 + q * 16,
                 &Bmat[(size_t)(k0 + r) * NTOT + n_blk + q * 8]);
        }
        cp_commit();
    };

    auto compute = [&](int ch) {
        const uint32_t stg = sb + (ch % NSTAGE) * STG;
        const int k0 = ch * 32;
#pragma unroll
        for (int ks = 0; ks < 2; ks++) {
            const int kk = ks * 16;
            uint32_t bfrag[8][2];
#pragma unroll
            for (int h = 0; h < 4; h++) {
                uint32_t r0, r1, r2, r3;
                uint32_t a = stg + ASTG + (kk + (lane & 15)) * 528
                           + (wn0 + h * 16 + (lane >> 4) * 8) * 2;
                ldsm_x4t(r0, r1, r2, r3, a);
                bfrag[h * 2][0] = r0;     bfrag[h * 2][1] = r1;
                bfrag[h * 2 + 1][0] = r2; bfrag[h * 2 + 1][1] = r3;
            }
            uint32_t kvlo = *(const uint32_t*)&skv[k0 + kk + (lane & 3) * 2];
            uint32_t kvhi = *(const uint32_t*)&skv[k0 + kk + 8 + (lane & 3) * 2];
#pragma unroll
            for (int term = 0; term < 2; term++) {
#pragma unroll
                for (int mt = 0; mt < 4; mt++) {
                    uint32_t afrag[4];
                    uint32_t a = stg + term * 10240
                               + (wm0 + mt * 16 + (lane & 15)) * 80
                               + (kk + (lane >> 4) * 8) * 2;
                    ldsm_x4(afrag[0], afrag[1], afrag[2], afrag[3], a);
                    __half2* af = (__half2*)afrag;
                    __half2 lo = *(__half2*)&kvlo, hi = *(__half2*)&kvhi;
                    af[0] = __hmul2(af[0], lo); af[1] = __hmul2(af[1], lo);
                    af[2] = __hmul2(af[2], hi); af[3] = __hmul2(af[3], hi);
#pragma unroll
                    for (int nt = 0; nt < 8; nt++)
                        mma_f16(acc[mt][nt], afrag, bfrag[nt]);
                }
            }
        }
    };

    issue(0); issue(1); issue(2);
#pragma unroll
    for (int ch = 0; ch < 12; ch++) {
        int rem = 11 - ch;
        if (rem >= 2) cp_wait<2>(); else if (rem == 1) cp_wait<1>(); else cp_wait<0>();
        __syncthreads();
        compute(ch);
        __syncthreads();
        if (ch + 3 < 12) issue(ch + 3);
    }

    const int g = lane >> 2, tig = lane & 3;
#pragma unroll
    for (int mt = 0; mt < 4; mt++) {
#pragma unroll
        for (int i = 0; i < 2; i++) {
            int row = m_blk + wm0 + mt * 16 + g + i * 8;
            float sc = g_scale[row_off + row] * WSCI;
            float bi = g_bias[row_off + row];
#pragma unroll
            for (int nt = 0; nt < 8; nt++) {
#pragma unroll
                for (int j = 0; j < 2; j++) {
                    int n = wn0 + nt * 8 + tig * 2 + j;
                    float val = acc[mt][nt][i * 2 + j] * sc + bi;
                    size_t oi = ((size_t)tb * Cd + row) * HWd + n;
                    out[oi] = val + identity[oi];
                }
            }
        }
    }
}

// ---------------------------------------------------------------------------
__global__ void kv_kernel()
{
    int bc = blockIdx.x;
    int c = bc % Cd, b = bc / Cd;
    int n = threadIdx.x;
    float p[Td];
#pragma unroll
    for (int t = 0; t < Td; t++) {
        size_t o = (size_t)(t * Bd + b) * HWd + n;
        float kk = __half2float(g_sqkv[(size_t)(Cd + c) * NTOT + o]);
        float vv = __half2float(g_sqkv[(size_t)(2 * Cd + c) * NTOT + o]);
        p[t] = kk * vv;
    }
#pragma unroll
    for (int t = 0; t < Td; t++)
        for (int o = 16; o > 0; o >>= 1) p[t] += __shfl_down_sync(0xffffffffu, p[t], o);
    __shared__ float wsum[Td][8];
    int lane = n & 31, wid = n >> 5;
    if (lane == 0)
#pragma unroll
        for (int t = 0; t < Td; t++) wsum[t][wid] = p[t];
    __syncthreads();
    if (n == 0) {
        float v = 0.f;
#pragma unroll
        for (int t = 0; t < Td; t++) {
            float kvp = 0.f;
#pragma unroll
            for (int w = 0; w < 8; w++) kvp += wsum[t][w];
            v = 0.5f * (v + kvp);
            float s = (v >= 0.5f) ? 1.f : 0.f;
            v *= (1.f - s);
            g_kvs[(size_t)(t * Bd + b) * Cd + c] = __float2half(s);
        }
    }
}

// ---------------------------------------------------------------------------
__global__ void vout_kernel(float* __restrict__ out2)
{
    int tid = blockIdx.x * 256 + threadIdx.x;    // NELEM exact
    int ch = tid % CHD;
    int rest = tid / CHD;
    int n = rest % HWd;
    rest /= HWd;
    int head = rest % HEADS;
    int tb = rest / HEADS;
    int c = head * CHD + ch;
    out2[tid] = __half2float(g_sqkv[(size_t)(2 * Cd + c) * NTOT + (size_t)tb * HWd + n]);
}

// ---------------------------------------------------------------------------
extern "C" void kernel_launch(void* const* d_in, const int* in_sizes, int n_in,
                              void* d_out, int out_size)
{
    const float* x   = (const float*)d_in[0];
    const float* qw  = (const float*)d_in[1];
    const float* qg  = (const float*)d_in[2];
    const float* qb  = (const float*)d_in[3];
    const float* qm  = (const float*)d_in[4];
    const float* qv  = (const float*)d_in[5];
    const float* kw  = (const float*)d_in[6];
    const float* kg  = (const float*)d_in[7];
    const float* kb  = (const float*)d_in[8];
    const float* km  = (const float*)d_in[9];
    const float* kv  = (const float*)d_in[10];
    const float* vw  = (const float*)d_in[11];
    const float* vg  = (const float*)d_in[12];
    const float* vb  = (const float*)d_in[13];
    const float* vm  = (const float*)d_in[14];
    const float* vv  = (const float*)d_in[15];
    const float* pw  = (const float*)d_in[16];
    const float* pb  = (const float*)d_in[17];
    const float* pg  = (const float*)d_in[18];
    const float* pbe = (const float*)d_in[19];
    const float* pm  = (const float*)d_in[20];
    const float* pv  = (const float*)d_in[21];

    cudaFuncSetAttribute(mma_gemm<0>, cudaFuncAttributeMaxDynamicSharedMemorySize, DSMEM);
    cudaFuncSetAttribute(mma_gemm_proj, cudaFuncAttributeMaxDynamicSharedMemorySize, DSMEM);

    __half *p_sx, *p_sq;
    cudaGetSymbolAddress((void**)&p_sx, g_sx);
    cudaGetSymbolAddress((void**)&p_sq, g_sqkv);

    float* out = (float*)d_out;

    prep_kernel<<<1, 384>>>(qg, qb, qm, qv, kg, kb, km, kv, vg, vb, vm, vv,
                            pb, pg, pbe, pm, pv);
    wsplit_kernel<<<2304, 256>>>(qw, kw, vw, pw);
    lif_x_kernel<<<12288, 256>>>(x);

    dim3 g1(Bd * 4, 9);                           // 128 (b,n0) tiles x 9 row-tiles
    mma_gemm<0><<<g1, 256, DSMEM>>>(p_sx, nullptr, 0);

    kv_kernel<<<Bd * Cd, 256>>>();

    dim3 g2(Td * Bd, 3);                          // 128 tb x 3 row-tiles
    mma_gemm_proj<<<g2, 256, DSMEM>>>(p_sq, out, x);

    if (out_size >= 2 * NELEM)
        vout_kernel<<<NELEM / 256, 256>>>(out + NELEM);
}

// round 8
// speedup vs baseline: 4.5218x; 1.1005x over previous
#include <cuda_runtime.h>
#include <cuda_fp16.h>
#include <cstdint>

#define Td 4
#define Bd 32
#define Cd 384
#define HWd 256
#define NTOT 32768          // Td*Bd*HWd
#define HEADS 8
#define CHD 48
#define EPSB 1e-5f
#define NELEM 12582912      // Td*Bd*Cd*HWd
#define WSC 16384.0f
#define WSCI 6.103515625e-05f   // 1/16384

#define ASTG 20480          // A stage: 2 terms * 128 rows * 40 halves * 2B
#define BSTG 16896          // B stage: 32 rows * 264 halves * 2B
#define STG  (ASTG + BSTG)  // 37376
#define NSTAGE 4
#define DSMEM (NSTAGE * STG)   // 149504

// ---- scratch ----
__device__ __half g_sx[Cd * NTOT];            // shortcut-LIF spikes [c][(t*B+b)*HW+n]
__device__ __half g_sqkv[3 * Cd * NTOT];      // q,k,v spikes (rows 0..1151)
__device__ __half g_kvs[Td * Bd * Cd];        // talking-heads spikes [tb][c]
__device__ __half g_w[2][4 * Cd][Cd];         // 2-term fp16 split weights (x16384)
__device__ float  g_scale[4 * Cd];
__device__ float  g_bias[4 * Cd];

// ---------------------------------------------------------------------------
__device__ __forceinline__ uint32_t cvta_smem(const void* p) {
    uint32_t a;
    asm("{ .reg .u64 t; cvta.to.shared.u64 t, %1; cvt.u32.u64 %0, t; }" : "=r"(a) : "l"(p));
    return a;
}
__device__ __forceinline__ void cp16(uint32_t d, const void* s) {
    asm volatile("cp.async.cg.shared.global [%0], [%1], 16;" :: "r"(d), "l"(s));
}
__device__ __forceinline__ void cp_commit() {
    asm volatile("cp.async.commit_group;" ::: "memory");
}
template <int N>
__device__ __forceinline__ void cp_wait() {
    asm volatile("cp.async.wait_group %0;" :: "n"(N) : "memory");
}
__device__ __forceinline__ void ldsm_x4(uint32_t* r, uint32_t a) {
    asm volatile("ldmatrix.sync.aligned.m8n8.x4.shared.b16 {%0,%1,%2,%3},[%4];"
                 : "=r"(r[0]), "=r"(r[1]), "=r"(r[2]), "=r"(r[3]) : "r"(a));
}
__device__ __forceinline__ void ldsm_x4t(uint32_t& r0, uint32_t& r1, uint32_t& r2, uint32_t& r3, uint32_t a) {
    asm volatile("ldmatrix.sync.aligned.m8n8.x4.trans.shared.b16 {%0,%1,%2,%3},[%4];"
                 : "=r"(r0), "=r"(r1), "=r"(r2), "=r"(r3) : "r"(a));
}
__device__ __forceinline__ void mma_f16(float* d, const uint32_t* a, const uint32_t* b) {
    asm volatile("mma.sync.aligned.m16n8k16.row.col.f32.f16.f16.f32 "
                 "{%0,%1,%2,%3},{%4,%5,%6,%7},{%8,%9},{%0,%1,%2,%3};"
                 : "+f"(d[0]), "+f"(d[1]), "+f"(d[2]), "+f"(d[3])
                 : "r"(a[0]), "r"(a[1]), "r"(a[2]), "r"(a[3]), "r"(b[0]), "r"(b[1]));
}

// ---------------------------------------------------------------------------
__global__ void prep_kernel(
    const float* qg, const float* qb, const float* qm, const float* qv,
    const float* kg, const float* kb, const float* km, const float* kvv,
    const float* vg, const float* vb, const float* vm, const float* vvv,
    const float* pb, const float* pg, const float* pbe, const float* pm, const float* pv)
{
    int d = threadIdx.x;
    if (d >= Cd) return;
    float s;
    s = qg[d] * rsqrtf(qv[d] + EPSB);  g_scale[d]          = s; g_bias[d]          = qb[d] - qm[d] * s;
    s = kg[d] * rsqrtf(kvv[d] + EPSB); g_scale[Cd + d]     = s; g_bias[Cd + d]     = kb[d] - km[d] * s;
    s = vg[d] * rsqrtf(vvv[d] + EPSB); g_scale[2*Cd + d]   = s; g_bias[2*Cd + d]   = vb[d] - vm[d] * s;
    s = pg[d] * rsqrtf(pv[d] + EPSB);  g_scale[3*Cd + d]   = s; g_bias[3*Cd + d]   = (pb[d] - pm[d]) * s + pbe[d];
}

__global__ void wsplit_kernel(const float* __restrict__ qw, const float* __restrict__ kw,
                              const float* __restrict__ vw, const float* __restrict__ pw)
{
    int tid = blockIdx.x * 256 + threadIdx.x;      // 1536*384 exact
    int row = tid / Cd, cin = tid - row * Cd;
    const float* src = (row < Cd) ? qw : (row < 2*Cd) ? kw : (row < 3*Cd) ? vw : pw;
    float a = src[(row % Cd) * Cd + cin] * WSC;
    __half h1 = __float2half_rn(a);
    float r1 = a - __half2float(h1);
    g_w[0][row][cin] = h1;
    g_w[1][row][cin] = __float2half_rn(r1);
}

// ---------------------------------------------------------------------------
__global__ void lif_x_kernel(const float* __restrict__ x)
{
    int tid = blockIdx.x * 256 + threadIdx.x;      // Bd*Cd*HWd exact
    int n = tid % HWd;
    int c = (tid / HWd) % Cd;
    int b = tid / (HWd * Cd);
    float v = 0.f;
#pragma unroll
    for (int t = 0; t < Td; t++) {
        float xv = x[(size_t)((t * Bd + b) * Cd + c) * HWd + n];
        v = 0.5f * (v + xv);
        float s = (v >= 1.0f) ? 1.f : 0.f;
        v *= (1.f - s);
        g_sx[(size_t)c * NTOT + (size_t)(t * Bd + b) * HWd + n] = __float2half(s);
    }
}

// ---------------------------------------------------------------------------
// Pipelined tensor-core GEMM, block 128(M) x 256(N) x 32(K), warps 2x4,
// warp tile 64x64, 4-stage cp.async, hoisted A fragments.
// qkv: B = g_sx; N-tile = one b, 64 n x 4 t interleaved; epilogue = LIF.
// ---------------------------------------------------------------------------
__global__ void __launch_bounds__(256) mma_gemm_qkv(const __half* __restrict__ Bmat)
{
    extern __shared__ char dsm[];
    const uint32_t sb = cvta_smem(dsm);

    const int tid = threadIdx.x;
    const int warp = tid >> 5, lane = tid & 31;
    const int wm0 = (warp >> 2) * 64, wn0 = (warp & 3) * 64;
    const int m_blk = blockIdx.y * 128;
    const int b  = blockIdx.x >> 2;
    const int n0 = (blockIdx.x & 3) * 64;

    float acc[4][8][4];
#pragma unroll
    for (int i = 0; i < 4; i++)
#pragma unroll
        for (int j = 0; j < 8; j++)
#pragma unroll
            for (int r = 0; r < 4; r++) acc[i][j][r] = 0.f;

    auto issue = [&](int ch) {
        const uint32_t stg = sb + (ch & 3) * STG;
        const int k0 = ch * 32;
#pragma unroll
        for (int it = 0; it < 4; it++) {          // A
            int o = tid + it * 256;
            int term = o >> 9, rem = o & 511;
            int r = rem >> 2, cq = rem & 3;
            cp16(stg + term * 10240 + r * 80 + cq * 16,
                 &g_w[term][m_blk + r][k0 + cq * 8]);
        }
#pragma unroll
        for (int it = 0; it < 4; it++) {          // B
            int o = tid + it * 256;
            int r = o >> 5, q = o & 31;
            int t = (q >> 1) & 3;
            int n = n0 + (q >> 3) * 16 + (q & 1) * 8;
            cp16(stg + ASTG + r * 528 + q * 16,
                 &Bmat[(size_t)(k0 + r) * NTOT + (size_t)(t * Bd + b) * HWd + n]);
        }
        cp_commit();
    };

    auto compute = [&](int ch) {
        const uint32_t stg = sb + (ch & 3) * STG;
#pragma unroll
        for (int ks = 0; ks < 2; ks++) {
            const int kk = ks * 16;
            uint32_t bfrag[8][2];
#pragma unroll
            for (int h = 0; h < 4; h++) {
                uint32_t r0, r1, r2, r3;
                uint32_t a = stg + ASTG + (kk + (lane & 15)) * 528
                           + (wn0 + h * 16 + (lane >> 4) * 8) * 2;
                ldsm_x4t(r0, r1, r2, r3, a);
                bfrag[h * 2][0] = r0;     bfrag[h * 2][1] = r1;
                bfrag[h * 2 + 1][0] = r2; bfrag[h * 2 + 1][1] = r3;
            }
            uint32_t afr[2][4][4];
#pragma unroll
            for (int term = 0; term < 2; term++)
#pragma unroll
                for (int mt = 0; mt < 4; mt++)
                    ldsm_x4(afr[term][mt],
                            stg + term * 10240
                            + (wm0 + mt * 16 + (lane & 15)) * 80
                            + (kk + (lane >> 4) * 8) * 2);
#pragma unroll
            for (int term = 0; term < 2; term++)
#pragma unroll
                for (int mt = 0; mt < 4; mt++)
#pragma unroll
                    for (int nt = 0; nt < 8; nt++)
                        mma_f16(acc[mt][nt], afr[term][mt], bfrag[nt]);
        }
    };

    issue(0); issue(1); issue(2);
#pragma unroll
    for (int ch = 0; ch < 12; ch++) {
        int rem = 11 - ch;
        if (rem >= 2) cp_wait<2>(); else if (rem == 1) cp_wait<1>(); else cp_wait<0>();
        __syncthreads();
        if (ch + 3 < 12) issue(ch + 3);
        compute(ch);
    }

    const int g = lane >> 2, tig = lane & 3;
#pragma unroll
    for (int mt = 0; mt < 4; mt++) {
#pragma unroll
        for (int i = 0; i < 2; i++) {
            int row = m_blk + wm0 + mt * 16 + g + i * 8;
            float sc = g_scale[row] * WSCI;
            float bi = g_bias[row];
#pragma unroll
            for (int r = 0; r < 2; r++) {
#pragma unroll
                for (int j = 0; j < 2; j++) {
                    int n = n0 + (warp & 3) * 16 + r * 8 + tig * 2 + j;
                    float v = 0.f;
#pragma unroll
                    for (int t = 0; t < Td; t++) {
                        float z = acc[mt][2 * t + r][i * 2 + j] * sc + bi;
                        v = 0.5f * (v + z);
                        float s = (v >= 1.0f) ? 1.f : 0.f;
                        v *= (1.f - s);
                        g_sqkv[(size_t)row * NTOT + (size_t)(t * Bd + b) * HWd + n] =
                            __float2half(s);
                    }
                }
            }
        }
    }
}

// ---------------------------------------------------------------------------
// proj GEMM: B = q-spikes of one tb (256 cols); A fragments * kv (binary).
// Epilogue: scatter (tb,c,n) + identity.
// ---------------------------------------------------------------------------
__global__ void __launch_bounds__(256) mma_gemm_proj(
    const __half* __restrict__ Bmat, float* __restrict__ out,
    const float* __restrict__ identity)
{
    extern __shared__ char dsm[];
    __shared__ __half skv[Cd];
    const uint32_t sb = cvta_smem(dsm);
    const int row_off = 3 * Cd;

    const int tid = threadIdx.x;
    const int warp = tid >> 5, lane = tid & 31;
    const int wm0 = (warp >> 2) * 64, wn0 = (warp & 3) * 64;
    const int m_blk = blockIdx.y * 128;
    const int tb = blockIdx.x;
    const int n_blk = tb * 256;

    for (int i = tid; i < Cd; i += 256) skv[i] = g_kvs[(size_t)tb * Cd + i];

    float acc[4][8][4];
#pragma unroll
    for (int i = 0; i < 4; i++)
#pragma unroll
        for (int j = 0; j < 8; j++)
#pragma unroll
            for (int r = 0; r < 4; r++) acc[i][j][r] = 0.f;

    auto issue = [&](int ch) {
        const uint32_t stg = sb + (ch & 3) * STG;
        const int k0 = ch * 32;
#pragma unroll
        for (int it = 0; it < 4; it++) {
            int o = tid + it * 256;
            int term = o >> 9, rem = o & 511;
            int r = rem >> 2, cq = rem & 3;
            cp16(stg + term * 10240 + r * 80 + cq * 16,
                 &g_w[term][row_off + m_blk + r][k0 + cq * 8]);
        }
#pragma unroll
        for (int it = 0; it < 4; it++) {
            int o = tid + it * 256;
            int r = o >> 5, q = o & 31;
            cp16(stg + ASTG + r * 528 + q * 16,
                 &Bmat[(size_t)(k0 + r) * NTOT + n_blk + q * 8]);
        }
        cp_commit();
    };

    auto compute = [&](int ch) {
        const uint32_t stg = sb + (ch & 3) * STG;
        const int k0 = ch * 32;
#pragma unroll
        for (int ks = 0; ks < 2; ks++) {
            const int kk = ks * 16;
            uint32_t bfrag[8][2];
#pragma unroll
            for (int h = 0; h < 4; h++) {
                uint32_t r0, r1, r2, r3;
                uint32_t a = stg + ASTG + (kk + (lane & 15)) * 528
                           + (wn0 + h * 16 + (lane >> 4) * 8) * 2;
                ldsm_x4t(r0, r1, r2, r3, a);
                bfrag[h * 2][0] = r0;     bfrag[h * 2][1] = r1;
                bfrag[h * 2 + 1][0] = r2; bfrag[h * 2 + 1][1] = r3;
            }
            uint32_t kvlo = *(const uint32_t*)&skv[k0 + kk + (lane & 3) * 2];
            uint32_t kvhi = *(const uint32_t*)&skv[k0 + kk + 8 + (lane & 3) * 2];
            __half2 lo = *(__half2*)&kvlo, hi = *(__half2*)&kvhi;
            uint32_t afr[2][4][4];
#pragma unroll
            for (int term = 0; term < 2; term++)
#pragma unroll
                for (int mt = 0; mt < 4; mt++) {
                    ldsm_x4(afr[term][mt],
                            stg + term * 10240
                            + (wm0 + mt * 16 + (lane & 15)) * 80
                            + (kk + (lane >> 4) * 8) * 2);
                    __half2* af = (__half2*)afr[term][mt];
                    af[0] = __hmul2(af[0], lo); af[1] = __hmul2(af[1], lo);
                    af[2] = __hmul2(af[2], hi); af[3] = __hmul2(af[3], hi);
                }
#pragma unroll
            for (int term = 0; term < 2; term++)
#pragma unroll
                for (int mt = 0; mt < 4; mt++)
#pragma unroll
                    for (int nt = 0; nt < 8; nt++)
                        mma_f16(acc[mt][nt], afr[term][mt], bfrag[nt]);
        }
    };

    issue(0); issue(1); issue(2);
#pragma unroll
    for (int ch = 0; ch < 12; ch++) {
        int rem = 11 - ch;
        if (rem >= 2) cp_wait<2>(); else if (rem == 1) cp_wait<1>(); else cp_wait<0>();
        __syncthreads();
        if (ch + 3 < 12) issue(ch + 3);
        compute(ch);
    }

    const int g = lane >> 2, tig = lane & 3;
#pragma unroll
    for (int mt = 0; mt < 4; mt++) {
#pragma unroll
        for (int i = 0; i < 2; i++) {
            int row = m_blk + wm0 + mt * 16 + g + i * 8;
            float sc = g_scale[row_off + row] * WSCI;
            float bi = g_bias[row_off + row];
#pragma unroll
            for (int nt = 0; nt < 8; nt++) {
#pragma unroll
                for (int j = 0; j < 2; j++) {
                    int n = wn0 + nt * 8 + tig * 2 + j;
                    float val = acc[mt][nt][i * 2 + j] * sc + bi;
                    size_t oi = ((size_t)tb * Cd + row) * HWd + n;
                    out[oi] = val + identity[oi];
                }
            }
        }
    }
}

// ---------------------------------------------------------------------------
__global__ void kv_kernel()
{
    int bc = blockIdx.x;
    int c = bc % Cd, b = bc / Cd;
    int n = threadIdx.x;
    float p[Td];
#pragma unroll
    for (int t = 0; t < Td; t++) {
        size_t o = (size_t)(t * Bd + b) * HWd + n;
        float kk = __half2float(g_sqkv[(size_t)(Cd + c) * NTOT + o]);
        float vv = __half2float(g_sqkv[(size_t)(2 * Cd + c) * NTOT + o]);
        p[t] = kk * vv;
    }
#pragma unroll
    for (int t = 0; t < Td; t++)
        for (int o = 16; o > 0; o >>= 1) p[t] += __shfl_down_sync(0xffffffffu, p[t], o);
    __shared__ float wsum[Td][8];
    int lane = n & 31, wid = n >> 5;
    if (lane == 0)
#pragma unroll
        for (int t = 0; t < Td; t++) wsum[t][wid] = p[t];
    __syncthreads();
    if (n == 0) {
        float v = 0.f;
#pragma unroll
        for (int t = 0; t < Td; t++) {
            float kvp = 0.f;
#pragma unroll
            for (int w = 0; w < 8; w++) kvp += wsum[t][w];
            v = 0.5f * (v + kvp);
            float s = (v >= 0.5f) ? 1.f : 0.f;
            v *= (1.f - s);
            g_kvs[(size_t)(t * Bd + b) * Cd + c] = __float2half(s);
        }
    }
}

// ---------------------------------------------------------------------------
// v spikes -> (T,B,heads,N,Ch) via smem transpose: coalesced both sides.
// Block = (tb, head): 48 channels x 256 n.
// ---------------------------------------------------------------------------
__global__ void vout_kernel(float* __restrict__ out2)
{
    __shared__ __half s[CHD][HWd + 8];
    int tb = blockIdx.x, head = blockIdx.y;
    int tid = threadIdx.x;                    // 256
#pragma unroll
    for (int ch = 0; ch < CHD; ch++)
        s[ch][tid] = g_sqkv[(size_t)(2 * Cd + head * CHD + ch) * NTOT
                            + (size_t)tb * HWd + tid];
    __syncthreads();
#pragma unroll
    for (int it = 0; it < CHD; it++) {
        int idx = it * 256 + tid;             // 48*256 elems
        int ch = idx % CHD, n = idx / CHD;
        out2[((size_t)(tb * HEADS + head) * HWd + n) * CHD + ch] =
            __half2float(s[ch][n]);
    }
}

// ---------------------------------------------------------------------------
extern "C" void kernel_launch(void* const* d_in, const int* in_sizes, int n_in,
                              void* d_out, int out_size)
{
    const float* x   = (const float*)d_in[0];
    const float* qw  = (const float*)d_in[1];
    const float* qg  = (const float*)d_in[2];
    const float* qb  = (const float*)d_in[3];
    const float* qm  = (const float*)d_in[4];
    const float* qv  = (const float*)d_in[5];
    const float* kw  = (const float*)d_in[6];
    const float* kg  = (const float*)d_in[7];
    const float* kb  = (const float*)d_in[8];
    const float* km  = (const float*)d_in[9];
    const float* kv  = (const float*)d_in[10];
    const float* vw  = (const float*)d_in[11];
    const float* vg  = (const float*)d_in[12];
    const float* vb  = (const float*)d_in[13];
    const float* vm  = (const float*)d_in[14];
    const float* vv  = (const float*)d_in[15];
    const float* pw  = (const float*)d_in[16];
    const float* pb  = (const float*)d_in[17];
    const float* pg  = (const float*)d_in[18];
    const float* pbe = (const float*)d_in[19];
    const float* pm  = (const float*)d_in[20];
    const float* pv  = (const float*)d_in[21];

    cudaFuncSetAttribute(mma_gemm_qkv, cudaFuncAttributeMaxDynamicSharedMemorySize, DSMEM);
    cudaFuncSetAttribute(mma_gemm_proj, cudaFuncAttributeMaxDynamicSharedMemorySize, DSMEM);

    __half *p_sx, *p_sq;
    cudaGetSymbolAddress((void**)&p_sx, g_sx);
    cudaGetSymbolAddress((void**)&p_sq, g_sqkv);

    float* out = (float*)d_out;

    prep_kernel<<<1, 384>>>(qg, qb, qm, qv, kg, kb, km, kv, vg, vb, vm, vv,
                            pb, pg, pbe, pm, pv);
    wsplit_kernel<<<2304, 256>>>(qw, kw, vw, pw);
    lif_x_kernel<<<12288, 256>>>(x);

    dim3 g1(Bd * 4, 9);                           // 128 (b,n0) tiles x 9 row-tiles
    mma_gemm_qkv<<<g1, 256, DSMEM>>>(p_sx);

    kv_kernel<<<Bd * Cd, 256>>>();

    dim3 g2(Td * Bd, 3);                          // 128 tb x 3 row-tiles
    mma_gemm_proj<<<g2, 256, DSMEM>>>(p_sq, out, x);

    if (out_size >= 2 * NELEM)
        vout_kernel<<<dim3(Td * Bd, HEADS), 256>>>(out + NELEM);
}

// round 9
// speedup vs baseline: 4.8492x; 1.0724x over previous
#include <cuda_runtime.h>
#include <cuda_fp16.h>
#include <cstdint>

#define Td 4
#define Bd 32
#define Cd 384
#define HWd 256
#define NTOT 32768          // Td*Bd*HWd
#define HEADS 8
#define CHD 48
#define EPSB 1e-5f
#define NELEM 12582912      // Td*Bd*Cd*HWd
#define WSC 16384.0f
#define WSCI 6.103515625e-05f   // 1/16384

#define ASTG 20480          // qkv A stage: 2 terms * 128 rows * 40 halves * 2B
#define BSTG 16896          // B stage: 32 rows * 264 halves * 2B
#define STG  (ASTG + BSTG)  // 37376
#define DSMEM (4 * STG)     // 149504

#define ASTG_P 10240        // proj A stage: 1 term
#define STG_P (ASTG_P + BSTG)   // 27136
#define DSMEM_P (4 * STG_P)     // 108544

// ---- scratch ----
__device__ __half g_sx[Cd * NTOT];            // shortcut-LIF spikes [c][(t*B+b)*HW+n]
__device__ __half g_sqkv[3 * Cd * NTOT];      // q,k,v spikes (rows 0..1151)
__device__ __half g_kvs[Td * Bd * Cd];        // talking-heads spikes [tb][c]
__device__ __half g_w[2][4 * Cd][Cd];         // 2-term fp16 split weights (x16384)
__device__ float  g_scale[4 * Cd];
__device__ float  g_bias[4 * Cd];

// ---------------------------------------------------------------------------
__device__ __forceinline__ uint32_t cvta_smem(const void* p) {
    uint32_t a;
    asm("{ .reg .u64 t; cvta.to.shared.u64 t, %1; cvt.u32.u64 %0, t; }" : "=r"(a) : "l"(p));
    return a;
}
__device__ __forceinline__ void cp16(uint32_t d, const void* s) {
    asm volatile("cp.async.cg.shared.global [%0], [%1], 16;" :: "r"(d), "l"(s));
}
__device__ __forceinline__ void cp_commit() {
    asm volatile("cp.async.commit_group;" ::: "memory");
}
template <int N>
__device__ __forceinline__ void cp_wait() {
    asm volatile("cp.async.wait_group %0;" :: "n"(N) : "memory");
}
__device__ __forceinline__ void ldsm_x4(uint32_t* r, uint32_t a) {
    asm volatile("ldmatrix.sync.aligned.m8n8.x4.shared.b16 {%0,%1,%2,%3},[%4];"
                 : "=r"(r[0]), "=r"(r[1]), "=r"(r[2]), "=r"(r[3]) : "r"(a));
}
__device__ __forceinline__ void ldsm_x4t(uint32_t& r0, uint32_t& r1, uint32_t& r2, uint32_t& r3, uint32_t a) {
    asm volatile("ldmatrix.sync.aligned.m8n8.x4.trans.shared.b16 {%0,%1,%2,%3},[%4];"
                 : "=r"(r0), "=r"(r1), "=r"(r2), "=r"(r3) : "r"(a));
}
__device__ __forceinline__ void mma_f16(float* d, const uint32_t* a, const uint32_t* b) {
    asm volatile("mma.sync.aligned.m16n8k16.row.col.f32.f16.f16.f32 "
                 "{%0,%1,%2,%3},{%4,%5,%6,%7},{%8,%9},{%0,%1,%2,%3};"
                 : "+f"(d[0]), "+f"(d[1]), "+f"(d[2]), "+f"(d[3])
                 : "r"(a[0]), "r"(a[1]), "r"(a[2]), "r"(a[3]), "r"(b[0]), "r"(b[1]));
}

// ---------------------------------------------------------------------------
__global__ void prep_kernel(
    const float* qg, const float* qb, const float* qm, const float* qv,
    const float* kg, const float* kb, const float* km, const float* kvv,
    const float* vg, const float* vb, const float* vm, const float* vvv,
    const float* pb, const float* pg, const float* pbe, const float* pm, const float* pv)
{
    int d = threadIdx.x;
    if (d >= Cd) return;
    float s;
    s = qg[d] * rsqrtf(qv[d] + EPSB);  g_scale[d]          = s; g_bias[d]          = qb[d] - qm[d] * s;
    s = kg[d] * rsqrtf(kvv[d] + EPSB); g_scale[Cd + d]     = s; g_bias[Cd + d]     = kb[d] - km[d] * s;
    s = vg[d] * rsqrtf(vvv[d] + EPSB); g_scale[2*Cd + d]   = s; g_bias[2*Cd + d]   = vb[d] - vm[d] * s;
    s = pg[d] * rsqrtf(pv[d] + EPSB);  g_scale[3*Cd + d]   = s; g_bias[3*Cd + d]   = (pb[d] - pm[d]) * s + pbe[d];
}

__global__ void wsplit_kernel(const float* __restrict__ qw, const float* __restrict__ kw,
                              const float* __restrict__ vw, const float* __restrict__ pw)
{
    int tid = blockIdx.x * 256 + threadIdx.x;      // 1536*384 exact
    int row = tid / Cd, cin = tid - row * Cd;
    const float* src = (row < Cd) ? qw : (row < 2*Cd) ? kw : (row < 3*Cd) ? vw : pw;
    float a = src[(row % Cd) * Cd + cin] * WSC;
    __half h1 = __float2half_rn(a);
    float r1 = a - __half2float(h1);
    g_w[0][row][cin] = h1;
    g_w[1][row][cin] = __float2half_rn(r1);
}

// ---------------------------------------------------------------------------
__global__ void lif_x_kernel(const float* __restrict__ x)
{
    int tid = blockIdx.x * 256 + threadIdx.x;      // Bd*Cd*HWd exact
    int n = tid % HWd;
    int c = (tid / HWd) % Cd;
    int b = tid / (HWd * Cd);
    float v = 0.f;
#pragma unroll
    for (int t = 0; t < Td; t++) {
        float xv = x[(size_t)((t * Bd + b) * Cd + c) * HWd + n];
        v = 0.5f * (v + xv);
        float s = (v >= 1.0f) ? 1.f : 0.f;
        v *= (1.f - s);
        g_sx[(size_t)c * NTOT + (size_t)(t * Bd + b) * HWd + n] = __float2half(s);
    }
}

// ---------------------------------------------------------------------------
// qkv GEMM, block 128(M) x 256(N=64n x 4t) x 32(K), warps 2x4, 4-stage.
// Epilogue: temporal LIF -> spikes; v-row CTAs also write out2 via smem stage.
// ---------------------------------------------------------------------------
__global__ void __launch_bounds__(256) mma_gemm_qkv(const __half* __restrict__ Bmat,
                                                    float* __restrict__ out2)
{
    extern __shared__ char dsm[];
    const uint32_t sb = cvta_smem(dsm);

    const int tid = threadIdx.x;
    const int warp = tid >> 5, lane = tid & 31;
    const int wm0 = (warp >> 2) * 64, wn0 = (warp & 3) * 64;
    const int m_blk = blockIdx.y * 128;
    const int b  = blockIdx.x >> 2;
    const int n0 = (blockIdx.x & 3) * 64;

    float acc[4][8][4];
#pragma unroll
    for (int i = 0; i < 4; i++)
#pragma unroll
        for (int j = 0; j < 8; j++)
#pragma unroll
            for (int r = 0; r < 4; r++) acc[i][j][r] = 0.f;

    auto issue = [&](int ch) {
        const uint32_t stg = sb + (ch & 3) * STG;
        const int k0 = ch * 32;
#pragma unroll
        for (int it = 0; it < 4; it++) {          // A
            int o = tid + it * 256;
            int term = o >> 9, rem = o & 511;
            int r = rem >> 2, cq = rem & 3;
            cp16(stg + term * 10240 + r * 80 + cq * 16,
                 &g_w[term][m_blk + r][k0 + cq * 8]);
        }
#pragma unroll
        for (int it = 0; it < 4; it++) {          // B
            int o = tid + it * 256;
            int r = o >> 5, q = o & 31;
            int t = (q >> 1) & 3;
            int n = n0 + (q >> 3) * 16 + (q & 1) * 8;
            cp16(stg + ASTG + r * 528 + q * 16,
                 &Bmat[(size_t)(k0 + r) * NTOT + (size_t)(t * Bd + b) * HWd + n]);
        }
        cp_commit();
    };

    auto compute = [&](int ch) {
        const uint32_t stg = sb + (ch & 3) * STG;
#pragma unroll
        for (int ks = 0; ks < 2; ks++) {
            const int kk = ks * 16;
            uint32_t bfrag[8][2];
#pragma unroll
            for (int h = 0; h < 4; h++) {
                uint32_t r0, r1, r2, r3;
                uint32_t a = stg + ASTG + (kk + (lane & 15)) * 528
                           + (wn0 + h * 16 + (lane >> 4) * 8) * 2;
                ldsm_x4t(r0, r1, r2, r3, a);
                bfrag[h * 2][0] = r0;     bfrag[h * 2][1] = r1;
                bfrag[h * 2 + 1][0] = r2; bfrag[h * 2 + 1][1] = r3;
            }
            uint32_t afr[2][4][4];
#pragma unroll
            for (int term = 0; term < 2; term++)
#pragma unroll
                for (int mt = 0; mt < 4; mt++)
                    ldsm_x4(afr[term][mt],
                            stg + term * 10240
                            + (wm0 + mt * 16 + (lane & 15)) * 80
                            + (kk + (lane >> 4) * 8) * 2);
#pragma unroll
            for (int term = 0; term < 2; term++)
#pragma unroll
                for (int mt = 0; mt < 4; mt++)
#pragma unroll
                    for (int nt = 0; nt < 8; nt++)
                        mma_f16(acc[mt][nt], afr[term][mt], bfrag[nt]);
        }
    };

    issue(0); issue(1); issue(2);
#pragma unroll
    for (int ch = 0; ch < 12; ch++) {
        int rem = 11 - ch;
        if (rem >= 2) cp_wait<2>(); else if (rem == 1) cp_wait<1>(); else cp_wait<0>();
        __syncthreads();
        if (ch + 3 < 12) issue(ch + 3);
        compute(ch);
    }

    const bool vtile = (m_blk >= 2 * Cd);
    __half* sv = reinterpret_cast<__half*>(dsm);   // [t][n_l 64][row_l 128]
    if (vtile) __syncthreads();                    // mainloop done before smem reuse

    const int g = lane >> 2, tig = lane & 3;
#pragma unroll
    for (int mt = 0; mt < 4; mt++) {
#pragma unroll
        for (int i = 0; i < 2; i++) {
            int rl = wm0 + mt * 16 + g + i * 8;
            int row = m_blk + rl;
            float sc = g_scale[row] * WSCI;
            float bi = g_bias[row];
#pragma unroll
            for (int r = 0; r < 2; r++) {
#pragma unroll
                for (int j = 0; j < 2; j++) {
                    int n = n0 + (warp & 3) * 16 + r * 8 + tig * 2 + j;
                    float v = 0.f;
#pragma unroll
                    for (int t = 0; t < Td; t++) {
                        float z = acc[mt][2 * t + r][i * 2 + j] * sc + bi;
                        v = 0.5f * (v + z);
                        float s = (v >= 1.0f) ? 1.f : 0.f;
                        v *= (1.f - s);
                        __half hs = __float2half(s);
                        g_sqkv[(size_t)row * NTOT + (size_t)(t * Bd + b) * HWd + n] = hs;
                        if (vtile) sv[(t * 64 + (n - n0)) * 128 + rl] = hs;
                    }
                }
            }
        }
    }

    if (vtile) {
        __syncthreads();
        int c0 = m_blk - 2 * Cd;
#pragma unroll
        for (int it = 0; it < 128; it++) {
            int idx = tid + it * 256;               // 32768 = 4t*64n*128row
            int rl = idx & 127;
            int nl = (idx >> 7) & 63;
            int t = idx >> 13;
            int c = c0 + rl;
            int head = c / CHD, ch = c - head * CHD;
            int tb = t * Bd + b;
            out2[((size_t)(tb * HEADS + head) * HWd + n0 + nl) * CHD + ch] =
                __half2float(sv[(t * 64 + nl) * 128 + rl]);
        }
    }
}

// ---------------------------------------------------------------------------
// proj GEMM: single fp16 term; B = q-spikes of one tb; A * kv (binary).
// Epilogue: scatter (tb,c,n) + identity.
// ---------------------------------------------------------------------------
__global__ void __launch_bounds__(256) mma_gemm_proj(
    const __half* __restrict__ Bmat, float* __restrict__ out,
    const float* __restrict__ identity)
{
    extern __shared__ char dsm[];
    __shared__ __half skv[Cd];
    const uint32_t sb = cvta_smem(dsm);
    const int row_off = 3 * Cd;

    const int tid = threadIdx.x;
    const int warp = tid >> 5, lane = tid & 31;
    const int wm0 = (warp >> 2) * 64, wn0 = (warp & 3) * 64;
    const int m_blk = blockIdx.y * 128;
    const int tb = blockIdx.x;
    const int n_blk = tb * 256;

    for (int i = tid; i < Cd; i += 256) skv[i] = g_kvs[(size_t)tb * Cd + i];

    float acc[4][8][4];
#pragma unroll
    for (int i = 0; i < 4; i++)
#pragma unroll
        for (int j = 0; j < 8; j++)
#pragma unroll
            for (int r = 0; r < 4; r++) acc[i][j][r] = 0.f;

    auto issue = [&](int ch) {
        const uint32_t stg = sb + (ch & 3) * STG_P;
        const int k0 = ch * 32;
#pragma unroll
        for (int it = 0; it < 2; it++) {          // A: 512 cp16
            int o = tid + it * 256;
            int r = o >> 2, cq = o & 3;
            cp16(stg + r * 80 + cq * 16, &g_w[0][row_off + m_blk + r][k0 + cq * 8]);
        }
#pragma unroll
        for (int it = 0; it < 4; it++) {          // B: 1024 cp16
            int o = tid + it * 256;
            int r = o >> 5, q = o & 31;
            cp16(stg + ASTG_P + r * 528 + q * 16,
                 &Bmat[(size_t)(k0 + r) * NTOT + n_blk + q * 8]);
        }
        cp_commit();
    };

    auto compute = [&](int ch) {
        const uint32_t stg = sb + (ch & 3) * STG_P;
        const int k0 = ch * 32;
#pragma unroll
        for (int ks = 0; ks < 2; ks++) {
            const int kk = ks * 16;
            uint32_t bfrag[8][2];
#pragma unroll
            for (int h = 0; h < 4; h++) {
                uint32_t r0, r1, r2, r3;
                uint32_t a = stg + ASTG_P + (kk + (lane & 15)) * 528
                           + (wn0 + h * 16 + (lane >> 4) * 8) * 2;
                ldsm_x4t(r0, r1, r2, r3, a);
                bfrag[h * 2][0] = r0;     bfrag[h * 2][1] = r1;
                bfrag[h * 2 + 1][0] = r2; bfrag[h * 2 + 1][1] = r3;
            }
            uint32_t kvlo = *(const uint32_t*)&skv[k0 + kk + (lane & 3) * 2];
            uint32_t kvhi = *(const uint32_t*)&skv[k0 + kk + 8 + (lane & 3) * 2];
            __half2 lo = *(__half2*)&kvlo, hi = *(__half2*)&kvhi;
            uint32_t afr[4][4];
#pragma unroll
            for (int mt = 0; mt < 4; mt++) {
                ldsm_x4(afr[mt],
                        stg + (wm0 + mt * 16 + (lane & 15)) * 80
                        + (kk + (lane >> 4) * 8) * 2);
                __half2* af = (__half2*)afr[mt];
                af[0] = __hmul2(af[0], lo); af[1] = __hmul2(af[1], lo);
                af[2] = __hmul2(af[2], hi); af[3] = __hmul2(af[3], hi);
            }
#pragma unroll
            for (int mt = 0; mt < 4; mt++)
#pragma unroll
                for (int nt = 0; nt < 8; nt++)
                    mma_f16(acc[mt][nt], afr[mt], bfrag[nt]);
        }
    };

    issue(0); issue(1); issue(2);
#pragma unroll
    for (int ch = 0; ch < 12; ch++) {
        int rem = 11 - ch;
        if (rem >= 2) cp_wait<2>(); else if (rem == 1) cp_wait<1>(); else cp_wait<0>();
        __syncthreads();
        if (ch + 3 < 12) issue(ch + 3);
        compute(ch);
    }

    const int g = lane >> 2, tig = lane & 3;
#pragma unroll
    for (int mt = 0; mt < 4; mt++) {
#pragma unroll
        for (int i = 0; i < 2; i++) {
            int row = m_blk + wm0 + mt * 16 + g + i * 8;
            float sc = g_scale[row_off + row] * WSCI;
            float bi = g_bias[row_off + row];
#pragma unroll
            for (int nt = 0; nt < 8; nt++) {
#pragma unroll
                for (int j = 0; j < 2; j++) {
                    int n = wn0 + nt * 8 + tig * 2 + j;
                    float val = acc[mt][nt][i * 2 + j] * sc + bi;
                    size_t oi = ((size_t)tb * Cd + row) * HWd + n;
                    out[oi] = val + identity[oi];
                }
            }
        }
    }
}

// ---------------------------------------------------------------------------
__global__ void kv_kernel()
{
    int bc = blockIdx.x;
    int c = bc % Cd, b = bc / Cd;
    int n = threadIdx.x;
    float p[Td];
#pragma unroll
    for (int t = 0; t < Td; t++) {
        size_t o = (size_t)(t * Bd + b) * HWd + n;
        float kk = __half2float(g_sqkv[(size_t)(Cd + c) * NTOT + o]);
        float vv = __half2float(g_sqkv[(size_t)(2 * Cd + c) * NTOT + o]);
        p[t] = kk * vv;
    }
#pragma unroll
    for (int t = 0; t < Td; t++)
        for (int o = 16; o > 0; o >>= 1) p[t] += __shfl_down_sync(0xffffffffu, p[t], o);
    __shared__ float wsum[Td][8];
    int lane = n & 31, wid = n >> 5;
    if (lane == 0)
#pragma unroll
        for (int t = 0; t < Td; t++) wsum[t][wid] = p[t];
    __syncthreads();
    if (n == 0) {
        float v = 0.f;
#pragma unroll
        for (int t = 0; t < Td; t++) {
            float kvp = 0.f;
#pragma unroll
            for (int w = 0; w < 8; w++) kvp += wsum[t][w];
            v = 0.5f * (v + kvp);
            float s = (v >= 0.5f) ? 1.f : 0.f;
            v *= (1.f - s);
            g_kvs[(size_t)(t * Bd + b) * Cd + c] = __float2half(s);
        }
    }
}

// ---------------------------------------------------------------------------
extern "C" void kernel_launch(void* const* d_in, const int* in_sizes, int n_in,
                              void* d_out, int out_size)
{
    const float* x   = (const float*)d_in[0];
    const float* qw  = (const float*)d_in[1];
    const float* qg  = (const float*)d_in[2];
    const float* qb  = (const float*)d_in[3];
    const float* qm  = (const float*)d_in[4];
    const float* qv  = (const float*)d_in[5];
    const float* kw  = (const float*)d_in[6];
    const float* kg  = (const float*)d_in[7];
    const float* kb  = (const float*)d_in[8];
    const float* km  = (const float*)d_in[9];
    const float* kv  = (const float*)d_in[10];
    const float* vw  = (const float*)d_in[11];
    const float* vg  = (const float*)d_in[12];
    const float* vb  = (const float*)d_in[13];
    const float* vm  = (const float*)d_in[14];
    const float* vv  = (const float*)d_in[15];
    const float* pw  = (const float*)d_in[16];
    const float* pb  = (const float*)d_in[17];
    const float* pg  = (const float*)d_in[18];
    const float* pbe = (const float*)d_in[19];
    const float* pm  = (const float*)d_in[20];
    const float* pv  = (const float*)d_in[21];

    cudaFuncSetAttribute(mma_gemm_qkv, cudaFuncAttributeMaxDynamicSharedMemorySize, DSMEM);
    cudaFuncSetAttribute(mma_gemm_proj, cudaFuncAttributeMaxDynamicSharedMemorySize, DSMEM_P);

    __half *p_sx, *p_sq;
    cudaGetSymbolAddress((void**)&p_sx, g_sx);
    cudaGetSymbolAddress((void**)&p_sq, g_sqkv);

    float* out = (float*)d_out;

    prep_kernel<<<1, 384>>>(qg, qb, qm, qv, kg, kb, km, kv, vg, vb, vm, vv,
                            pb, pg, pbe, pm, pv);
    wsplit_kernel<<<2304, 256>>>(qw, kw, vw, pw);
    lif_x_kernel<<<12288, 256>>>(x);

    dim3 g1(Bd * 4, 9);                           // 128 (b,n0) tiles x 9 row-tiles
    mma_gemm_qkv<<<g1, 256, DSMEM>>>(p_sx, out + NELEM);

    kv_kernel<<<Bd * Cd, 256>>>();

    dim3 g2(Td * Bd, 3);                          // 128 tb x 3 row-tiles
    mma_gemm_proj<<<g2, 256, DSMEM_P>>>(p_sq, out, x);
}